// round 5
// baseline (speedup 1.0000x reference)
#include <cuda_runtime.h>
#include <cuda_bf16.h>
#include <cstdint>
#include <cstddef>

// Problem constants
#define BB   2
#define SS   2048
#define DIMM 2048
#define HH   16
#define KVHH 4
#define HDD  128
// M = B*S = 4096, QKV N = 3072, K = 2048

// ---------------------------------------------------------------------------
// Scratch (static device globals; no allocation anywhere)
// ---------------------------------------------------------------------------
__device__ float g_wqkv[(size_t)3072 * 2048];          // concat [wq;wk;wv], row-major [3072][2048]
__device__ float g_qkv [(size_t)4096 * 3072];          // qkv = x @ Wqkv^T, [4096][3072]
__device__ float g_q   [(size_t)BB * HH  * SS * HDD];  // [b][h][s][hd], roped + 1/sqrt(hd) scaled
__device__ float g_k   [(size_t)BB * KVHH * SS * HDD]; // [b][kvh][s][hd], roped
__device__ float g_v   [(size_t)BB * KVHH * SS * HDD]; // [b][kvh][s][hd]
__device__ float g_attn[(size_t)4096 * 2048];          // [b*s][h*hd]

// ---------------------------------------------------------------------------
// Kernel 1: concatenate wq/wk/wv into one [3072][2048] weight matrix
// ---------------------------------------------------------------------------
__global__ void concat_w_kernel(const float* __restrict__ wq,
                                const float* __restrict__ wk,
                                const float* __restrict__ wv,
                                float* __restrict__ dst)
{
    size_t i = (size_t)blockIdx.x * blockDim.x + threadIdx.x;   // float4 index
    size_t e = i * 4;
    const size_t NQ = (size_t)2048 * 2048;
    const size_t NK = (size_t)512 * 2048;
    if (e >= (size_t)3072 * 2048) return;
    const float* src;
    if (e < NQ)            src = wq + e;
    else if (e < NQ + NK)  src = wk + (e - NQ);
    else                   src = wv + (e - NQ - NK);
    *reinterpret_cast<float4*>(&dst[e]) = *reinterpret_cast<const float4*>(src);
}

// ---------------------------------------------------------------------------
// Kernel 2/5: SGEMM  C[m][n] = sum_k A[m][k] * B[n][k]   (A:[M,K], B:[N,K], C:[M,N])
// BM=BN=128, BK=16, 256 threads, 8x8 microtile, double-buffered smem.
// Requires M,N multiples of 128 and K multiple of 16.
// ---------------------------------------------------------------------------
__global__ __launch_bounds__(256, 2)
void sgemm_nt_kernel(const float* __restrict__ A, const float* __restrict__ B,
                     float* __restrict__ C, int M, int N, int K)
{
    __shared__ __align__(16) float As[2][16][132];
    __shared__ __align__(16) float Bs[2][16][132];

    const int bm = blockIdx.y * 128;
    const int bn = blockIdx.x * 128;
    const int tid = threadIdx.x;
    const int tx = tid & 15, ty = tid >> 4;

    const float* Aptr = A + (size_t)bm * K;
    const float* Bptr = B + (size_t)bn * K;

    float acc[8][8];
#pragma unroll
    for (int i = 0; i < 8; i++)
#pragma unroll
        for (int j = 0; j < 8; j++) acc[i][j] = 0.0f;

    // Prologue: load tile 0 directly into smem buffer 0
    {
#pragma unroll
        for (int s2 = 0; s2 < 2; s2++) {
            int f = tid * 2 + s2;            // 0..511 float4 units
            int r = f >> 2;                  // row within tile (0..127)
            int kq = f & 3;                  // which float4 along K (0..3)
            float4 av = *reinterpret_cast<const float4*>(&Aptr[(size_t)r * K + kq * 4]);
            As[0][kq * 4 + 0][r] = av.x;
            As[0][kq * 4 + 1][r] = av.y;
            As[0][kq * 4 + 2][r] = av.z;
            As[0][kq * 4 + 3][r] = av.w;
            float4 bv = *reinterpret_cast<const float4*>(&Bptr[(size_t)r * K + kq * 4]);
            Bs[0][kq * 4 + 0][r] = bv.x;
            Bs[0][kq * 4 + 1][r] = bv.y;
            Bs[0][kq * 4 + 2][r] = bv.z;
            Bs[0][kq * 4 + 3][r] = bv.w;
        }
    }
    __syncthreads();

    const int nt = K / 16;
    int buf = 0;
    for (int t = 0; t < nt; ++t) {
        float4 pa[2], pb[2];
        const bool more = (t + 1 < nt);
        if (more) {
            int k0n = (t + 1) * 16;
#pragma unroll
            for (int s2 = 0; s2 < 2; s2++) {
                int f = tid * 2 + s2;
                int r = f >> 2;
                int kq = f & 3;
                pa[s2] = *reinterpret_cast<const float4*>(&Aptr[(size_t)r * K + k0n + kq * 4]);
                pb[s2] = *reinterpret_cast<const float4*>(&Bptr[(size_t)r * K + k0n + kq * 4]);
            }
        }

#pragma unroll
        for (int kk = 0; kk < 16; kk++) {
            float a[8], b[8];
            *reinterpret_cast<float4*>(&a[0]) = *reinterpret_cast<const float4*>(&As[buf][kk][ty * 4]);
            *reinterpret_cast<float4*>(&a[4]) = *reinterpret_cast<const float4*>(&As[buf][kk][64 + ty * 4]);
            *reinterpret_cast<float4*>(&b[0]) = *reinterpret_cast<const float4*>(&Bs[buf][kk][tx * 4]);
            *reinterpret_cast<float4*>(&b[4]) = *reinterpret_cast<const float4*>(&Bs[buf][kk][64 + tx * 4]);
#pragma unroll
            for (int i = 0; i < 8; i++)
#pragma unroll
                for (int j = 0; j < 8; j++)
                    acc[i][j] += a[i] * b[j];
        }

        if (more) {
            int nb = buf ^ 1;
#pragma unroll
            for (int s2 = 0; s2 < 2; s2++) {
                int f = tid * 2 + s2;
                int r = f >> 2;
                int kq = f & 3;
                As[nb][kq * 4 + 0][r] = pa[s2].x;
                As[nb][kq * 4 + 1][r] = pa[s2].y;
                As[nb][kq * 4 + 2][r] = pa[s2].z;
                As[nb][kq * 4 + 3][r] = pa[s2].w;
                Bs[nb][kq * 4 + 0][r] = pb[s2].x;
                Bs[nb][kq * 4 + 1][r] = pb[s2].y;
                Bs[nb][kq * 4 + 2][r] = pb[s2].z;
                Bs[nb][kq * 4 + 3][r] = pb[s2].w;
            }
            buf = nb;
            __syncthreads();
        }
    }

    // Epilogue
#pragma unroll
    for (int ih = 0; ih < 2; ih++) {
#pragma unroll
        for (int i = 0; i < 4; i++) {
            int row = bm + ih * 64 + ty * 4 + i;
            int ai = ih * 4 + i;
            float4 v0 = make_float4(acc[ai][0], acc[ai][1], acc[ai][2], acc[ai][3]);
            float4 v1 = make_float4(acc[ai][4], acc[ai][5], acc[ai][6], acc[ai][7]);
            *reinterpret_cast<float4*>(&C[(size_t)row * N + bn + tx * 4])      = v0;
            *reinterpret_cast<float4*>(&C[(size_t)row * N + bn + 64 + tx * 4]) = v1;
        }
    }
}

// ---------------------------------------------------------------------------
// Kernel 3: RoPE + scatter.  Reads g_qkv [4096][3072]; writes
//   g_q [b][h][s][hd]  (roped, scaled by 1/sqrt(HD))
//   g_k [b][kvh][s][hd] (roped)
//   g_v [b][kvh][s][hd]
// One thread per (row, pair): 4096 * 1536 pairs.
// ---------------------------------------------------------------------------
__global__ void rope_scatter_kernel(const float* __restrict__ qkv,
                                    const float* __restrict__ fc,
                                    float* __restrict__ q_out,
                                    float* __restrict__ k_out,
                                    float* __restrict__ v_out)
{
    const float QSCALE = 0.08838834764831845f;  // 1/sqrt(128)
    size_t idx = (size_t)blockIdx.x * blockDim.x + threadIdx.x;
    if (idx >= (size_t)4096 * 1536) return;
    int m = (int)(idx / 1536);
    int p = (int)(idx - (size_t)m * 1536);
    int n = p * 2;
    int b = m >> 11;          // m / 2048
    int s = m & 2047;

    float2 x2 = *reinterpret_cast<const float2*>(&qkv[(size_t)m * 3072 + n]);

    if (n < 2048) {                      // Q
        int h = n >> 7;
        int d = n & 127;
        float2 cs = *reinterpret_cast<const float2*>(&fc[(size_t)s * 128 + (d & ~1)]);
        float2 o;
        o.x = (x2.x * cs.x - x2.y * cs.y) * QSCALE;
        o.y = (x2.x * cs.y + x2.y * cs.x) * QSCALE;
        *reinterpret_cast<float2*>(&q_out[(((size_t)(b * HH + h) * SS + s) * HDD) + d]) = o;
    } else if (n < 2560) {               // K
        int nn = n - 2048;
        int h = nn >> 7;
        int d = nn & 127;
        float2 cs = *reinterpret_cast<const float2*>(&fc[(size_t)s * 128 + (d & ~1)]);
        float2 o;
        o.x = x2.x * cs.x - x2.y * cs.y;
        o.y = x2.x * cs.y + x2.y * cs.x;
        *reinterpret_cast<float2*>(&k_out[(((size_t)(b * KVHH + h) * SS + s) * HDD) + d]) = o;
    } else {                             // V (plain copy)
        int nn = n - 2560;
        int h = nn >> 7;
        int d = nn & 127;
        *reinterpret_cast<float2*>(&v_out[(((size_t)(b * KVHH + h) * SS + s) * HDD) + d]) = x2;
    }
}

// ---------------------------------------------------------------------------
// Kernel 4: causal GQA flash attention, fp32.
// BM=BN=64, HD=128, 256 threads (16x16). Scores microtile: 4 rows (4*ty+ii) x
// 4 cols (tx+16*jj). Output microtile: same 4 rows x 8 cols (32*c2 + 2*tx+{0,1}).
// K smem buffer is reused to hold P between the two GEMMs.
// Output layout: g_attn[(b*S+row)][h*128 + col] (ready for the wo GEMM).
// ---------------------------------------------------------------------------
#define FLASH_SMEM_BYTES (3 * 64 * 132 * 4)

__global__ __launch_bounds__(256, 2)
void flash_kernel(const float* __restrict__ gq, const float* __restrict__ gk,
                  const float* __restrict__ gv, float* __restrict__ gout)
{
    extern __shared__ __align__(16) float sm[];
    float (*Qs)[132] = reinterpret_cast<float(*)[132]>(sm);
    float (*Ks)[132] = reinterpret_cast<float(*)[132]>(sm + 64 * 132);   // reused as P
    float (*Vs)[132] = reinterpret_cast<float(*)[132]>(sm + 2 * 64 * 132);

    const int qb = (int)gridDim.x - 1 - (int)blockIdx.x;   // long blocks first
    const int bh = blockIdx.y;
    const int b = bh >> 4, h = bh & 15, kvh = h >> 2;

    const float* qbase = gq + ((size_t)(b * HH + h) * SS + (size_t)qb * 64) * HDD;
    const float* kbase = gk + (size_t)(b * KVHH + kvh) * SS * HDD;
    const float* vbase = gv + (size_t)(b * KVHH + kvh) * SS * HDD;

    const int tid = threadIdx.x;
    const int tx = tid & 15, ty = tid >> 4;

    // Load Q tile (already RoPE'd and pre-scaled by 1/sqrt(HD))
#pragma unroll
    for (int i = 0; i < 8; i++) {
        int f = tid + i * 256;           // float4 unit, 0..2047
        int r = f >> 5, c4 = f & 31;
        *reinterpret_cast<float4*>(&Qs[r][c4 * 4]) =
            *reinterpret_cast<const float4*>(&qbase[(size_t)r * HDD + c4 * 4]);
    }

    float m_i[4], l_i[4], acc[4][8];
#pragma unroll
    for (int ii = 0; ii < 4; ii++) {
        m_i[ii] = -1e30f;
        l_i[ii] = 0.0f;
#pragma unroll
        for (int c = 0; c < 8; c++) acc[ii][c] = 0.0f;
    }
    __syncthreads();

    for (int kt = 0; kt <= qb; ++kt) {
        const float* kb = kbase + (size_t)kt * 64 * HDD;
        const float* vb = vbase + (size_t)kt * 64 * HDD;
#pragma unroll
        for (int i = 0; i < 8; i++) {
            int f = tid + i * 256;
            int r = f >> 5, c4 = f & 31;
            *reinterpret_cast<float4*>(&Ks[r][c4 * 4]) =
                *reinterpret_cast<const float4*>(&kb[(size_t)r * HDD + c4 * 4]);
            *reinterpret_cast<float4*>(&Vs[r][c4 * 4]) =
                *reinterpret_cast<const float4*>(&vb[(size_t)r * HDD + c4 * 4]);
        }
        __syncthreads();

        // S = Q K^T (scores, already scaled through Q)
        float s[4][4];
#pragma unroll
        for (int ii = 0; ii < 4; ii++)
#pragma unroll
            for (int jj = 0; jj < 4; jj++) s[ii][jj] = 0.0f;

#pragma unroll 2
        for (int d = 0; d < 128; d += 2) {
            float2 q2[4], k2[4];
#pragma unroll
            for (int ii = 0; ii < 4; ii++)
                q2[ii] = *reinterpret_cast<const float2*>(&Qs[ty * 4 + ii][d]);
#pragma unroll
            for (int jj = 0; jj < 4; jj++)
                k2[jj] = *reinterpret_cast<const float2*>(&Ks[tx + 16 * jj][d]);
#pragma unroll
            for (int ii = 0; ii < 4; ii++)
#pragma unroll
                for (int jj = 0; jj < 4; jj++)
                    s[ii][jj] += q2[ii].x * k2[jj].x + q2[ii].y * k2[jj].y;
        }

        if (kt == qb) {  // diagonal tile: causal mask (local indices valid since BM==BN)
#pragma unroll
            for (int ii = 0; ii < 4; ii++)
#pragma unroll
                for (int jj = 0; jj < 4; jj++)
                    if (tx + 16 * jj > ty * 4 + ii) s[ii][jj] = -1e30f;
        }

        __syncthreads();   // everyone done reading Ks -> safe to reuse as P

        // Online softmax + write P into Ks buffer
#pragma unroll
        for (int ii = 0; ii < 4; ii++) {
            float mx = fmaxf(fmaxf(s[ii][0], s[ii][1]), fmaxf(s[ii][2], s[ii][3]));
#pragma unroll
            for (int off = 8; off > 0; off >>= 1)
                mx = fmaxf(mx, __shfl_xor_sync(0xffffffffu, mx, off));
            float mnew = fmaxf(m_i[ii], mx);
            float alpha = __expf(m_i[ii] - mnew);
            float p0 = __expf(s[ii][0] - mnew);
            float p1 = __expf(s[ii][1] - mnew);
            float p2 = __expf(s[ii][2] - mnew);
            float p3 = __expf(s[ii][3] - mnew);
            Ks[ty * 4 + ii][tx]      = p0;
            Ks[ty * 4 + ii][tx + 16] = p1;
            Ks[ty * 4 + ii][tx + 32] = p2;
            Ks[ty * 4 + ii][tx + 48] = p3;
            float ls = p0 + p1 + p2 + p3;
#pragma unroll
            for (int off = 8; off > 0; off >>= 1)
                ls += __shfl_xor_sync(0xffffffffu, ls, off);
            l_i[ii] = l_i[ii] * alpha + ls;
            m_i[ii] = mnew;
#pragma unroll
            for (int c = 0; c < 8; c++) acc[ii][c] *= alpha;
        }
        __syncthreads();   // P fully written

        // O += P @ V
#pragma unroll 4
        for (int j = 0; j < 64; j++) {
            float pr[4];
#pragma unroll
            for (int ii = 0; ii < 4; ii++) pr[ii] = Ks[ty * 4 + ii][j];
            float2 vv[4];
#pragma unroll
            for (int c2 = 0; c2 < 4; c2++)
                vv[c2] = *reinterpret_cast<const float2*>(&Vs[j][c2 * 32 + tx * 2]);
#pragma unroll
            for (int ii = 0; ii < 4; ii++)
#pragma unroll
                for (int c2 = 0; c2 < 4; c2++) {
                    acc[ii][2 * c2 + 0] += pr[ii] * vv[c2].x;
                    acc[ii][2 * c2 + 1] += pr[ii] * vv[c2].y;
                }
        }
        __syncthreads();   // done with P/V before next tile overwrites
    }

    // Epilogue: normalize and write to [b*S + row][h*128 + col]
    const size_t rowbase = (size_t)b * SS + (size_t)qb * 64;
#pragma unroll
    for (int ii = 0; ii < 4; ii++) {
        float inv = 1.0f / l_i[ii];
        size_t off = (rowbase + ty * 4 + ii) * (size_t)(HH * HDD) + (size_t)h * HDD;
#pragma unroll
        for (int c2 = 0; c2 < 4; c2++) {
            float2 o;
            o.x = acc[ii][2 * c2 + 0] * inv;
            o.y = acc[ii][2 * c2 + 1] * inv;
            *reinterpret_cast<float2*>(&gout[off + c2 * 32 + tx * 2]) = o;
        }
    }
}

// ---------------------------------------------------------------------------
// Host launcher
// ---------------------------------------------------------------------------
extern "C" void kernel_launch(void* const* d_in, const int* in_sizes, int n_in,
                              void* d_out, int out_size)
{
    (void)in_sizes; (void)n_in; (void)out_size;
    const float* x  = (const float*)d_in[0];
    const float* fc = (const float*)d_in[1];
    const float* wq = (const float*)d_in[2];
    const float* wk = (const float*)d_in[3];
    const float* wv = (const float*)d_in[4];
    const float* wo = (const float*)d_in[5];
    float* out = (float*)d_out;

    float *pwqkv, *pqkv, *pq, *pk, *pv, *pattn;
    cudaGetSymbolAddress((void**)&pwqkv, g_wqkv);
    cudaGetSymbolAddress((void**)&pqkv,  g_qkv);
    cudaGetSymbolAddress((void**)&pq,    g_q);
    cudaGetSymbolAddress((void**)&pk,    g_k);
    cudaGetSymbolAddress((void**)&pv,    g_v);
    cudaGetSymbolAddress((void**)&pattn, g_attn);

    // 1) concat weights: 3072*2048 floats = 1,572,864 float4s
    concat_w_kernel<<<6144, 256>>>(wq, wk, wv, pwqkv);

    // 2) QKV projection: [4096,2048] x [3072,2048]^T -> [4096,3072]
    sgemm_nt_kernel<<<dim3(3072 / 128, 4096 / 128), 256>>>(x, pwqkv, pqkv, 4096, 3072, 2048);

    // 3) RoPE + scatter into [b][head][s][hd] layouts (Q pre-scaled by 1/sqrt(HD))
    rope_scatter_kernel<<<24576, 256>>>(pqkv, fc, pq, pk, pv);

    // 4) causal GQA flash attention -> g_attn [4096][2048]
    cudaFuncSetAttribute(flash_kernel, cudaFuncAttributeMaxDynamicSharedMemorySize,
                         FLASH_SMEM_BYTES);
    flash_kernel<<<dim3(SS / 64, BB * HH), 256, FLASH_SMEM_BYTES>>>(pq, pk, pv, pattn);

    // 5) output projection: [4096,2048] x [2048,2048]^T -> out
    sgemm_nt_kernel<<<dim3(2048 / 128, 4096 / 128), 256>>>(pattn, wo, out, 4096, 2048, 2048);
}

// round 9
// speedup vs baseline: 1.4006x; 1.4006x over previous
#include <cuda_runtime.h>
#include <cuda_bf16.h>
#include <cstdint>
#include <cstddef>

// Problem constants
#define BB   2
#define SS   2048
#define DIMM 2048
#define HH   16
#define KVHH 4
#define HDD  128
// M = B*S = 4096, QKV N = 3072, K = 2048

// ---------------------------------------------------------------------------
// Scratch (static device globals; no allocation anywhere)
// ---------------------------------------------------------------------------
__device__ float g_qkv [(size_t)4096 * 3072];          // qkv = x @ Wqkv^T
__device__ float g_q   [(size_t)BB * HH  * SS * HDD];  // roped + scaled
__device__ float g_k   [(size_t)BB * KVHH * SS * HDD];
__device__ float g_v   [(size_t)BB * KVHH * SS * HDD];
__device__ float g_attn[(size_t)4096 * 2048];          // [b*s][h*hd]

__device__ __nv_bfloat16 g_x_h [(size_t)4096 * 2048];
__device__ __nv_bfloat16 g_x_l [(size_t)4096 * 2048];
__device__ __nv_bfloat16 g_w_h [(size_t)3072 * 2048];  // concat [wq;wk;wv]
__device__ __nv_bfloat16 g_w_l [(size_t)3072 * 2048];
__device__ __nv_bfloat16 g_ao_h[(size_t)4096 * 2048];
__device__ __nv_bfloat16 g_ao_l[(size_t)4096 * 2048];
__device__ __nv_bfloat16 g_wo_h[(size_t)2048 * 2048];
__device__ __nv_bfloat16 g_wo_l[(size_t)2048 * 2048];

// ---------------------------------------------------------------------------
// PTX helpers (sm_80+ baseline features only: cp.async + mma.sync)
// ---------------------------------------------------------------------------
__device__ __forceinline__ uint32_t s2u(const void* p) {
    uint32_t a;
    asm("{ .reg .u64 t; cvta.to.shared.u64 t, %1; cvt.u32.u64 %0, t; }" : "=r"(a) : "l"(p));
    return a;
}

#define CP_ASYNC16(dst, src) \
    asm volatile("cp.async.cg.shared.global [%0], [%1], 16;" :: "r"(dst), "l"(src) : "memory")
#define CP_COMMIT() asm volatile("cp.async.commit_group;" ::: "memory")
#define CP_WAIT(n)  asm volatile("cp.async.wait_group %0;" :: "n"(n) : "memory")

// D += A * B  (m16n8k16, row.col, bf16 in, fp32 acc)
#define MMA_BF16(acc, a, b) \
    asm volatile("mma.sync.aligned.m16n8k16.row.col.f32.bf16.bf16.f32 " \
                 "{%0,%1,%2,%3}, {%4,%5,%6,%7}, {%8,%9}, {%0,%1,%2,%3};" \
                 : "+f"((acc)[0]), "+f"((acc)[1]), "+f"((acc)[2]), "+f"((acc)[3]) \
                 : "r"((a)[0]), "r"((a)[1]), "r"((a)[2]), "r"((a)[3]), \
                   "r"((b)[0]), "r"((b)[1]))

// ---------------------------------------------------------------------------
// fp32 -> bf16 hi/lo split (elementwise, float4 per thread)
// ---------------------------------------------------------------------------
__global__ void cvt_split_kernel(const float* __restrict__ src,
                                 __nv_bfloat16* __restrict__ hi,
                                 __nv_bfloat16* __restrict__ lo, long n4)
{
    long i = (long)blockIdx.x * blockDim.x + threadIdx.x;
    if (i >= n4) return;
    float4 v = reinterpret_cast<const float4*>(src)[i];
    __nv_bfloat16 h0 = __float2bfloat16(v.x), h1 = __float2bfloat16(v.y);
    __nv_bfloat16 h2 = __float2bfloat16(v.z), h3 = __float2bfloat16(v.w);
    __nv_bfloat16 l0 = __float2bfloat16(v.x - __bfloat162float(h0));
    __nv_bfloat16 l1 = __float2bfloat16(v.y - __bfloat162float(h1));
    __nv_bfloat16 l2 = __float2bfloat16(v.z - __bfloat162float(h2));
    __nv_bfloat16 l3 = __float2bfloat16(v.w - __bfloat162float(h3));
    __nv_bfloat162 H0; H0.x = h0; H0.y = h1;
    __nv_bfloat162 H1; H1.x = h2; H1.y = h3;
    __nv_bfloat162 L0; L0.x = l0; L0.y = l1;
    __nv_bfloat162 L1; L1.x = l2; L1.y = l3;
    reinterpret_cast<__nv_bfloat162*>(hi + i * 4)[0] = H0;
    reinterpret_cast<__nv_bfloat162*>(hi + i * 4)[1] = H1;
    reinterpret_cast<__nv_bfloat162*>(lo + i * 4)[0] = L0;
    reinterpret_cast<__nv_bfloat162*>(lo + i * 4)[1] = L1;
}

// ---------------------------------------------------------------------------
// mma.sync split-bf16 GEMM: C[M,N] = A[M,K] * B[N,K]^T (fp32-equivalent)
//   C ~= Ah Bh^T + Ah Bl^T + Al Bh^T, fp32 accumulate.
// Tile 128x128, BK=32, 3-stage cp.async pipeline, 256 threads (8 warps 4x2,
// warp tile 32x64, m16n8k16 fragments via conflict-free LDS.32).
// smem tiles stored with 40-element (80 B) row stride: both the staged-store
// phases and the fragment-load lane->bank maps are conflict-free.
// ---------------------------------------------------------------------------
#define GBM 128
#define GBN 128
#define GBK 32
#define TILE_BYTES  (128 * 80)              // 128 rows x 40 bf16 (80 B)
#define STAGE_BYTES (4 * TILE_BYTES)        // Ah | Al | Bh | Bl
#define NSTAGE 3
#define GEMM_SMEM (NSTAGE * STAGE_BYTES)    // 122880 B

__global__ __launch_bounds__(256)
void tc_gemm_kernel(const __nv_bfloat16* __restrict__ Ah, const __nv_bfloat16* __restrict__ Al,
                    const __nv_bfloat16* __restrict__ Bh, const __nv_bfloat16* __restrict__ Bl,
                    float* __restrict__ C, int N, int K)
{
    extern __shared__ __align__(16) char smem[];
    const uint32_t smem_u = s2u(smem);
    const int tid  = threadIdx.x;
    const int lane = tid & 31;
    const int wid  = tid >> 5;
    const int g  = lane >> 2;      // group id (0..7)
    const int tg = lane & 3;       // thread-in-group (0..3)
    const int warpM = (wid >> 1) * 32;   // 4 warps along M
    const int warpN = (wid & 1) * 64;    // 2 warps along N
    const int bm = blockIdx.y * GBM;
    const int bn = blockIdx.x * GBN;
    const int nchunk = K / GBK;

    float acc[2][8][4];
#pragma unroll
    for (int mf = 0; mf < 2; mf++)
#pragma unroll
        for (int nf = 0; nf < 8; nf++)
#pragma unroll
            for (int r = 0; r < 4; r++) acc[mf][nf][r] = 0.0f;

    // ---- stage loader: 2048 x 16B transfers, 8 per thread -----------------
    auto load_stage = [&](int s, int c) {
        const int k0 = c * GBK;
        const uint32_t stg = smem_u + (uint32_t)s * STAGE_BYTES;
#pragma unroll
        for (int i = 0; i < 8; i++) {
            int f = tid + i * 256;
            int tile = f >> 9;        // 0:Ah 1:Al 2:Bh 3:Bl
            int fi = f & 511;
            int r = fi >> 2, q = fi & 3;
            const __nv_bfloat16* src;
            if (tile == 0)      src = Ah + (size_t)(bm + r) * K + k0 + q * 8;
            else if (tile == 1) src = Al + (size_t)(bm + r) * K + k0 + q * 8;
            else if (tile == 2) src = Bh + (size_t)(bn + r) * K + k0 + q * 8;
            else                src = Bl + (size_t)(bn + r) * K + k0 + q * 8;
            uint32_t dst = stg + (uint32_t)tile * TILE_BYTES + (uint32_t)r * 80 + q * 16;
            CP_ASYNC16(dst, src);
        }
    };

    // ---- compute one 128x128x32 stage -------------------------------------
    auto compute_stage = [&](int s) {
        const char* stg = smem + (size_t)s * STAGE_BYTES;
        const char* pAh = stg;
        const char* pAl = stg + TILE_BYTES;
        const char* pBh = stg + 2 * TILE_BYTES;
        const char* pBl = stg + 3 * TILE_BYTES;
#pragma unroll
        for (int ks = 0; ks < 2; ks++) {
            const int cb = (ks * 16 + tg * 2) * 2;   // byte offset along K
            uint32_t ah[2][4], al[2][4], bh[8][2], bl[8][2];
#pragma unroll
            for (int mf = 0; mf < 2; mf++) {
                const int r = warpM + mf * 16 + g;
                ah[mf][0] = *(const uint32_t*)(pAh + r * 80 + cb);
                ah[mf][1] = *(const uint32_t*)(pAh + (r + 8) * 80 + cb);
                ah[mf][2] = *(const uint32_t*)(pAh + r * 80 + cb + 16);
                ah[mf][3] = *(const uint32_t*)(pAh + (r + 8) * 80 + cb + 16);
                al[mf][0] = *(const uint32_t*)(pAl + r * 80 + cb);
                al[mf][1] = *(const uint32_t*)(pAl + (r + 8) * 80 + cb);
                al[mf][2] = *(const uint32_t*)(pAl + r * 80 + cb + 16);
                al[mf][3] = *(const uint32_t*)(pAl + (r + 8) * 80 + cb + 16);
            }
#pragma unroll
            for (int nf = 0; nf < 8; nf++) {
                const int r = warpN + nf * 8 + g;
                bh[nf][0] = *(const uint32_t*)(pBh + r * 80 + cb);
                bh[nf][1] = *(const uint32_t*)(pBh + r * 80 + cb + 16);
                bl[nf][0] = *(const uint32_t*)(pBl + r * 80 + cb);
                bl[nf][1] = *(const uint32_t*)(pBl + r * 80 + cb + 16);
            }
#pragma unroll
            for (int mf = 0; mf < 2; mf++)
#pragma unroll
                for (int nf = 0; nf < 8; nf++) {
                    MMA_BF16(acc[mf][nf], ah[mf], bh[nf]);
                    MMA_BF16(acc[mf][nf], ah[mf], bl[nf]);
                    MMA_BF16(acc[mf][nf], al[mf], bh[nf]);
                }
        }
    };

    // ---- pipeline ---------------------------------------------------------
    load_stage(0, 0); CP_COMMIT();
    load_stage(1, 1); CP_COMMIT();

    for (int c = 0; c < nchunk; ++c) {
        if (c + 2 < nchunk) { CP_WAIT(1); } else { CP_WAIT(0); }
        __syncthreads();
        if (c + 2 < nchunk) {
            load_stage((c + 2) % NSTAGE, c + 2);
            CP_COMMIT();
        }
        compute_stage(c % NSTAGE);
        __syncthreads();
    }

    // ---- epilogue ---------------------------------------------------------
#pragma unroll
    for (int mf = 0; mf < 2; mf++) {
        const int row0 = bm + warpM + mf * 16 + g;
#pragma unroll
        for (int nf = 0; nf < 8; nf++) {
            const int col = bn + warpN + nf * 8 + tg * 2;
            float2 v0 = make_float2(acc[mf][nf][0], acc[mf][nf][1]);
            float2 v1 = make_float2(acc[mf][nf][2], acc[mf][nf][3]);
            *reinterpret_cast<float2*>(&C[(size_t)row0 * N + col]) = v0;
            *reinterpret_cast<float2*>(&C[(size_t)(row0 + 8) * N + col]) = v1;
        }
    }
}

// ---------------------------------------------------------------------------
// RoPE + scatter (unchanged)
// ---------------------------------------------------------------------------
__global__ void rope_scatter_kernel(const float* __restrict__ qkv,
                                    const float* __restrict__ fc,
                                    float* __restrict__ q_out,
                                    float* __restrict__ k_out,
                                    float* __restrict__ v_out)
{
    const float QSCALE = 0.08838834764831845f;  // 1/sqrt(128)
    size_t idx = (size_t)blockIdx.x * blockDim.x + threadIdx.x;
    if (idx >= (size_t)4096 * 1536) return;
    int m = (int)(idx / 1536);
    int p = (int)(idx - (size_t)m * 1536);
    int n = p * 2;
    int b = m >> 11;
    int s = m & 2047;

    float2 x2 = *reinterpret_cast<const float2*>(&qkv[(size_t)m * 3072 + n]);

    if (n < 2048) {                      // Q
        int h = n >> 7;
        int d = n & 127;
        float2 cs = *reinterpret_cast<const float2*>(&fc[(size_t)s * 128 + (d & ~1)]);
        float2 o;
        o.x = (x2.x * cs.x - x2.y * cs.y) * QSCALE;
        o.y = (x2.x * cs.y + x2.y * cs.x) * QSCALE;
        *reinterpret_cast<float2*>(&q_out[(((size_t)(b * HH + h) * SS + s) * HDD) + d]) = o;
    } else if (n < 2560) {               // K
        int nn = n - 2048;
        int h = nn >> 7;
        int d = nn & 127;
        float2 cs = *reinterpret_cast<const float2*>(&fc[(size_t)s * 128 + (d & ~1)]);
        float2 o;
        o.x = x2.x * cs.x - x2.y * cs.y;
        o.y = x2.x * cs.y + x2.y * cs.x;
        *reinterpret_cast<float2*>(&k_out[(((size_t)(b * KVHH + h) * SS + s) * HDD) + d]) = o;
    } else {                             // V
        int nn = n - 2560;
        int h = nn >> 7;
        int d = nn & 127;
        *reinterpret_cast<float2*>(&v_out[(((size_t)(b * KVHH + h) * SS + s) * HDD) + d]) = x2;
    }
}

// ---------------------------------------------------------------------------
// Flash attention (unchanged fp32, known good)
// ---------------------------------------------------------------------------
#define FLASH_SMEM_BYTES (3 * 64 * 132 * 4)

__global__ __launch_bounds__(256, 2)
void flash_kernel(const float* __restrict__ gq, const float* __restrict__ gk,
                  const float* __restrict__ gv, float* __restrict__ gout)
{
    extern __shared__ __align__(16) float sm[];
    float (*Qs)[132] = reinterpret_cast<float(*)[132]>(sm);
    float (*Ks)[132] = reinterpret_cast<float(*)[132]>(sm + 64 * 132);   // reused as P
    float (*Vs)[132] = reinterpret_cast<float(*)[132]>(sm + 2 * 64 * 132);

    const int qb = (int)gridDim.x - 1 - (int)blockIdx.x;
    const int bh = blockIdx.y;
    const int b = bh >> 4, h = bh & 15, kvh = h >> 2;

    const float* qbase = gq + ((size_t)(b * HH + h) * SS + (size_t)qb * 64) * HDD;
    const float* kbase = gk + (size_t)(b * KVHH + kvh) * SS * HDD;
    const float* vbase = gv + (size_t)(b * KVHH + kvh) * SS * HDD;

    const int tid = threadIdx.x;
    const int tx = tid & 15, ty = tid >> 4;

#pragma unroll
    for (int i = 0; i < 8; i++) {
        int f = tid + i * 256;
        int r = f >> 5, c4 = f & 31;
        *reinterpret_cast<float4*>(&Qs[r][c4 * 4]) =
            *reinterpret_cast<const float4*>(&qbase[(size_t)r * HDD + c4 * 4]);
    }

    float m_i[4], l_i[4], acc[4][8];
#pragma unroll
    for (int ii = 0; ii < 4; ii++) {
        m_i[ii] = -1e30f;
        l_i[ii] = 0.0f;
#pragma unroll
        for (int c = 0; c < 8; c++) acc[ii][c] = 0.0f;
    }
    __syncthreads();

    for (int kt = 0; kt <= qb; ++kt) {
        const float* kb = kbase + (size_t)kt * 64 * HDD;
        const float* vb = vbase + (size_t)kt * 64 * HDD;
#pragma unroll
        for (int i = 0; i < 8; i++) {
            int f = tid + i * 256;
            int r = f >> 5, c4 = f & 31;
            *reinterpret_cast<float4*>(&Ks[r][c4 * 4]) =
                *reinterpret_cast<const float4*>(&kb[(size_t)r * HDD + c4 * 4]);
            *reinterpret_cast<float4*>(&Vs[r][c4 * 4]) =
                *reinterpret_cast<const float4*>(&vb[(size_t)r * HDD + c4 * 4]);
        }
        __syncthreads();

        float s[4][4];
#pragma unroll
        for (int ii = 0; ii < 4; ii++)
#pragma unroll
            for (int jj = 0; jj < 4; jj++) s[ii][jj] = 0.0f;

#pragma unroll 2
        for (int d = 0; d < 128; d += 2) {
            float2 q2[4], k2[4];
#pragma unroll
            for (int ii = 0; ii < 4; ii++)
                q2[ii] = *reinterpret_cast<const float2*>(&Qs[ty * 4 + ii][d]);
#pragma unroll
            for (int jj = 0; jj < 4; jj++)
                k2[jj] = *reinterpret_cast<const float2*>(&Ks[tx + 16 * jj][d]);
#pragma unroll
            for (int ii = 0; ii < 4; ii++)
#pragma unroll
                for (int jj = 0; jj < 4; jj++)
                    s[ii][jj] += q2[ii].x * k2[jj].x + q2[ii].y * k2[jj].y;
        }

        if (kt == qb) {
#pragma unroll
            for (int ii = 0; ii < 4; ii++)
#pragma unroll
                for (int jj = 0; jj < 4; jj++)
                    if (tx + 16 * jj > ty * 4 + ii) s[ii][jj] = -1e30f;
        }

        __syncthreads();

#pragma unroll
        for (int ii = 0; ii < 4; ii++) {
            float mx = fmaxf(fmaxf(s[ii][0], s[ii][1]), fmaxf(s[ii][2], s[ii][3]));
#pragma unroll
            for (int off = 8; off > 0; off >>= 1)
                mx = fmaxf(mx, __shfl_xor_sync(0xffffffffu, mx, off));
            float mnew = fmaxf(m_i[ii], mx);
            float alpha = __expf(m_i[ii] - mnew);
            float p0 = __expf(s[ii][0] - mnew);
            float p1 = __expf(s[ii][1] - mnew);
            float p2 = __expf(s[ii][2] - mnew);
            float p3 = __expf(s[ii][3] - mnew);
            Ks[ty * 4 + ii][tx]      = p0;
            Ks[ty * 4 + ii][tx + 16] = p1;
            Ks[ty * 4 + ii][tx + 32] = p2;
            Ks[ty * 4 + ii][tx + 48] = p3;
            float ls = p0 + p1 + p2 + p3;
#pragma unroll
            for (int off = 8; off > 0; off >>= 1)
                ls += __shfl_xor_sync(0xffffffffu, ls, off);
            l_i[ii] = l_i[ii] * alpha + ls;
            m_i[ii] = mnew;
#pragma unroll
            for (int c = 0; c < 8; c++) acc[ii][c] *= alpha;
        }
        __syncthreads();

#pragma unroll 4
        for (int j = 0; j < 64; j++) {
            float pr[4];
#pragma unroll
            for (int ii = 0; ii < 4; ii++) pr[ii] = Ks[ty * 4 + ii][j];
            float2 vv[4];
#pragma unroll
            for (int c2 = 0; c2 < 4; c2++)
                vv[c2] = *reinterpret_cast<const float2*>(&Vs[j][c2 * 32 + tx * 2]);
#pragma unroll
            for (int ii = 0; ii < 4; ii++)
#pragma unroll
                for (int c2 = 0; c2 < 4; c2++) {
                    acc[ii][2 * c2 + 0] += pr[ii] * vv[c2].x;
                    acc[ii][2 * c2 + 1] += pr[ii] * vv[c2].y;
                }
        }
        __syncthreads();
    }

    const size_t rowbase = (size_t)b * SS + (size_t)qb * 64;
#pragma unroll
    for (int ii = 0; ii < 4; ii++) {
        float inv = 1.0f / l_i[ii];
        size_t off = (rowbase + ty * 4 + ii) * (size_t)(HH * HDD) + (size_t)h * HDD;
#pragma unroll
        for (int c2 = 0; c2 < 4; c2++) {
            float2 o;
            o.x = acc[ii][2 * c2 + 0] * inv;
            o.y = acc[ii][2 * c2 + 1] * inv;
            *reinterpret_cast<float2*>(&gout[off + c2 * 32 + tx * 2]) = o;
        }
    }
}

// ---------------------------------------------------------------------------
// Host launcher
// ---------------------------------------------------------------------------
extern "C" void kernel_launch(void* const* d_in, const int* in_sizes, int n_in,
                              void* d_out, int out_size)
{
    (void)in_sizes; (void)n_in; (void)out_size;
    const float* x  = (const float*)d_in[0];
    const float* fc = (const float*)d_in[1];
    const float* wq = (const float*)d_in[2];
    const float* wk = (const float*)d_in[3];
    const float* wv = (const float*)d_in[4];
    const float* wo = (const float*)d_in[5];
    float* out = (float*)d_out;

    float *pqkv, *pq, *pk, *pv, *pattn;
    __nv_bfloat16 *pxh, *pxl, *pwh, *pwl, *paoh, *paol, *pwoh, *pwol;
    cudaGetSymbolAddress((void**)&pqkv,  g_qkv);
    cudaGetSymbolAddress((void**)&pq,    g_q);
    cudaGetSymbolAddress((void**)&pk,    g_k);
    cudaGetSymbolAddress((void**)&pv,    g_v);
    cudaGetSymbolAddress((void**)&pattn, g_attn);
    cudaGetSymbolAddress((void**)&pxh,   g_x_h);
    cudaGetSymbolAddress((void**)&pxl,   g_x_l);
    cudaGetSymbolAddress((void**)&pwh,   g_w_h);
    cudaGetSymbolAddress((void**)&pwl,   g_w_l);
    cudaGetSymbolAddress((void**)&paoh,  g_ao_h);
    cudaGetSymbolAddress((void**)&paol,  g_ao_l);
    cudaGetSymbolAddress((void**)&pwoh,  g_wo_h);
    cudaGetSymbolAddress((void**)&pwol,  g_wo_l);

    cudaFuncSetAttribute(tc_gemm_kernel, cudaFuncAttributeMaxDynamicSharedMemorySize, GEMM_SMEM);
    cudaFuncSetAttribute(flash_kernel, cudaFuncAttributeMaxDynamicSharedMemorySize,
                         FLASH_SMEM_BYTES);

    // Split-convert inputs to bf16 hi/lo
    {
        long n4 = (long)4096 * 2048 / 4;
        cvt_split_kernel<<<(unsigned)((n4 + 255) / 256), 256>>>(x, pxh, pxl, n4);
    }
    {
        long n4 = (long)2048 * 2048 / 4;
        cvt_split_kernel<<<(unsigned)((n4 + 255) / 256), 256>>>(wq, pwh, pwl, n4);
    }
    {
        long n4 = (long)512 * 2048 / 4;
        size_t off = (size_t)2048 * 2048;
        cvt_split_kernel<<<(unsigned)((n4 + 255) / 256), 256>>>(wk, pwh + off, pwl + off, n4);
        size_t off2 = (size_t)2560 * 2048;
        cvt_split_kernel<<<(unsigned)((n4 + 255) / 256), 256>>>(wv, pwh + off2, pwl + off2, n4);
    }

    // QKV projection on tensor cores (mma.sync): [4096,2048] x [3072,2048]^T
    tc_gemm_kernel<<<dim3(3072 / GBN, 4096 / GBM), 256, GEMM_SMEM>>>(
        pxh, pxl, pwh, pwl, pqkv, 3072, 2048);

    // RoPE + scatter
    rope_scatter_kernel<<<24576, 256>>>(pqkv, fc, pq, pk, pv);

    // Flash attention
    flash_kernel<<<dim3(SS / 64, BB * HH), 256, FLASH_SMEM_BYTES>>>(pq, pk, pv, pattn);

    // Split-convert attn + wo, then output projection on tensor cores
    {
        long n4 = (long)4096 * 2048 / 4;
        cvt_split_kernel<<<(unsigned)((n4 + 255) / 256), 256>>>(pattn, paoh, paol, n4);
    }
    {
        long n4 = (long)2048 * 2048 / 4;
        cvt_split_kernel<<<(unsigned)((n4 + 255) / 256), 256>>>(wo, pwoh, pwol, n4);
    }
    tc_gemm_kernel<<<dim3(2048 / GBN, 4096 / GBM), 256, GEMM_SMEM>>>(
        paoh, paol, pwoh, pwol, out, 2048, 2048);
}

// round 10
// speedup vs baseline: 2.2890x; 1.6343x over previous
#include <cuda_runtime.h>
#include <cuda_bf16.h>
#include <cstdint>
#include <cstddef>

// Problem constants
#define BB   2
#define SS   2048
#define DIMM 2048
#define HH   16
#define KVHH 4
#define HDD  128
// M = B*S = 4096, QKV N = 3072, K = 2048

// ---------------------------------------------------------------------------
// Scratch (static device globals; no allocation anywhere)
// ---------------------------------------------------------------------------
__device__ float g_qkv [(size_t)4096 * 3072];          // qkv = x @ Wqkv^T

__device__ __nv_bfloat16 g_x_h [(size_t)4096 * 2048];
__device__ __nv_bfloat16 g_x_l [(size_t)4096 * 2048];
__device__ __nv_bfloat16 g_w_h [(size_t)3072 * 2048];  // concat [wq;wk;wv]
__device__ __nv_bfloat16 g_w_l [(size_t)3072 * 2048];
__device__ __nv_bfloat16 g_ao_h[(size_t)4096 * 2048];  // attn out hi (flash writes)
__device__ __nv_bfloat16 g_ao_l[(size_t)4096 * 2048];
__device__ __nv_bfloat16 g_wo_h[(size_t)2048 * 2048];
__device__ __nv_bfloat16 g_wo_l[(size_t)2048 * 2048];

// flash operands, bf16 hi/lo
__device__ __nv_bfloat16 g_qh [(size_t)BB * HH  * SS * HDD];  // [b][h][s][hd] roped+scaled
__device__ __nv_bfloat16 g_ql [(size_t)BB * HH  * SS * HDD];
__device__ __nv_bfloat16 g_kh [(size_t)BB * KVHH * SS * HDD]; // [b][kvh][s][hd] roped
__device__ __nv_bfloat16 g_kl [(size_t)BB * KVHH * SS * HDD];
__device__ __nv_bfloat16 g_vth[(size_t)BB * KVHH * HDD * SS]; // [b][kvh][hd][s] transposed
__device__ __nv_bfloat16 g_vtl[(size_t)BB * KVHH * HDD * SS];

// ---------------------------------------------------------------------------
// PTX helpers (sm_80+ baseline: cp.async + mma.sync)
// ---------------------------------------------------------------------------
__device__ __forceinline__ uint32_t s2u(const void* p) {
    uint32_t a;
    asm("{ .reg .u64 t; cvta.to.shared.u64 t, %1; cvt.u32.u64 %0, t; }" : "=r"(a) : "l"(p));
    return a;
}

#define CP_ASYNC16(dst, src) \
    asm volatile("cp.async.cg.shared.global [%0], [%1], 16;" :: "r"(dst), "l"(src) : "memory")
#define CP_COMMIT() asm volatile("cp.async.commit_group;" ::: "memory")
#define CP_WAIT(n)  asm volatile("cp.async.wait_group %0;" :: "n"(n) : "memory")

// D += A * B  (m16n8k16, row.col, bf16 in, fp32 acc)
#define MMA_BF16(acc, a, b) \
    asm volatile("mma.sync.aligned.m16n8k16.row.col.f32.bf16.bf16.f32 " \
                 "{%0,%1,%2,%3}, {%4,%5,%6,%7}, {%8,%9}, {%0,%1,%2,%3};" \
                 : "+f"((acc)[0]), "+f"((acc)[1]), "+f"((acc)[2]), "+f"((acc)[3]) \
                 : "r"((a)[0]), "r"((a)[1]), "r"((a)[2]), "r"((a)[3]), \
                   "r"((b)[0]), "r"((b)[1]))

__device__ __forceinline__ uint32_t pack_bf16(float a, float b) {
    uint32_t lo = __bfloat16_as_ushort(__float2bfloat16(a));
    uint32_t hi = __bfloat16_as_ushort(__float2bfloat16(b));
    return lo | (hi << 16);
}

// ---------------------------------------------------------------------------
// fp32 -> bf16 hi/lo split (elementwise, float4 per thread)
// ---------------------------------------------------------------------------
__global__ void cvt_split_kernel(const float* __restrict__ src,
                                 __nv_bfloat16* __restrict__ hi,
                                 __nv_bfloat16* __restrict__ lo, long n4)
{
    long i = (long)blockIdx.x * blockDim.x + threadIdx.x;
    if (i >= n4) return;
    float4 v = reinterpret_cast<const float4*>(src)[i];
    __nv_bfloat16 h0 = __float2bfloat16(v.x), h1 = __float2bfloat16(v.y);
    __nv_bfloat16 h2 = __float2bfloat16(v.z), h3 = __float2bfloat16(v.w);
    __nv_bfloat16 l0 = __float2bfloat16(v.x - __bfloat162float(h0));
    __nv_bfloat16 l1 = __float2bfloat16(v.y - __bfloat162float(h1));
    __nv_bfloat16 l2 = __float2bfloat16(v.z - __bfloat162float(h2));
    __nv_bfloat16 l3 = __float2bfloat16(v.w - __bfloat162float(h3));
    __nv_bfloat162 H0; H0.x = h0; H0.y = h1;
    __nv_bfloat162 H1; H1.x = h2; H1.y = h3;
    __nv_bfloat162 L0; L0.x = l0; L0.y = l1;
    __nv_bfloat162 L1; L1.x = l2; L1.y = l3;
    reinterpret_cast<__nv_bfloat162*>(hi + i * 4)[0] = H0;
    reinterpret_cast<__nv_bfloat162*>(hi + i * 4)[1] = H1;
    reinterpret_cast<__nv_bfloat162*>(lo + i * 4)[0] = L0;
    reinterpret_cast<__nv_bfloat162*>(lo + i * 4)[1] = L1;
}

// ---------------------------------------------------------------------------
// mma.sync split-bf16 GEMM (unchanged from round 9, known good)
// ---------------------------------------------------------------------------
#define GBM 128
#define GBN 128
#define GBK 32
#define TILE_BYTES  (128 * 80)
#define STAGE_BYTES (4 * TILE_BYTES)
#define NSTAGE 3
#define GEMM_SMEM (NSTAGE * STAGE_BYTES)

__global__ __launch_bounds__(256)
void tc_gemm_kernel(const __nv_bfloat16* __restrict__ Ah, const __nv_bfloat16* __restrict__ Al,
                    const __nv_bfloat16* __restrict__ Bh, const __nv_bfloat16* __restrict__ Bl,
                    float* __restrict__ C, int N, int K)
{
    extern __shared__ __align__(16) char smem[];
    const uint32_t smem_u = s2u(smem);
    const int tid  = threadIdx.x;
    const int lane = tid & 31;
    const int wid  = tid >> 5;
    const int g  = lane >> 2;
    const int tg = lane & 3;
    const int warpM = (wid >> 1) * 32;
    const int warpN = (wid & 1) * 64;
    const int bm = blockIdx.y * GBM;
    const int bn = blockIdx.x * GBN;
    const int nchunk = K / GBK;

    float acc[2][8][4];
#pragma unroll
    for (int mf = 0; mf < 2; mf++)
#pragma unroll
        for (int nf = 0; nf < 8; nf++)
#pragma unroll
            for (int r = 0; r < 4; r++) acc[mf][nf][r] = 0.0f;

    auto load_stage = [&](int s, int c) {
        const int k0 = c * GBK;
        const uint32_t stg = smem_u + (uint32_t)s * STAGE_BYTES;
#pragma unroll
        for (int i = 0; i < 8; i++) {
            int f = tid + i * 256;
            int tile = f >> 9;
            int fi = f & 511;
            int r = fi >> 2, q = fi & 3;
            const __nv_bfloat16* src;
            if (tile == 0)      src = Ah + (size_t)(bm + r) * K + k0 + q * 8;
            else if (tile == 1) src = Al + (size_t)(bm + r) * K + k0 + q * 8;
            else if (tile == 2) src = Bh + (size_t)(bn + r) * K + k0 + q * 8;
            else                src = Bl + (size_t)(bn + r) * K + k0 + q * 8;
            uint32_t dst = stg + (uint32_t)tile * TILE_BYTES + (uint32_t)r * 80 + q * 16;
            CP_ASYNC16(dst, src);
        }
    };

    auto compute_stage = [&](int s) {
        const char* stg = smem + (size_t)s * STAGE_BYTES;
        const char* pAh = stg;
        const char* pAl = stg + TILE_BYTES;
        const char* pBh = stg + 2 * TILE_BYTES;
        const char* pBl = stg + 3 * TILE_BYTES;
#pragma unroll
        for (int ks = 0; ks < 2; ks++) {
            const int cb = (ks * 16 + tg * 2) * 2;
            uint32_t ah[2][4], al[2][4], bh[8][2], bl[8][2];
#pragma unroll
            for (int mf = 0; mf < 2; mf++) {
                const int r = warpM + mf * 16 + g;
                ah[mf][0] = *(const uint32_t*)(pAh + r * 80 + cb);
                ah[mf][1] = *(const uint32_t*)(pAh + (r + 8) * 80 + cb);
                ah[mf][2] = *(const uint32_t*)(pAh + r * 80 + cb + 16);
                ah[mf][3] = *(const uint32_t*)(pAh + (r + 8) * 80 + cb + 16);
                al[mf][0] = *(const uint32_t*)(pAl + r * 80 + cb);
                al[mf][1] = *(const uint32_t*)(pAl + (r + 8) * 80 + cb);
                al[mf][2] = *(const uint32_t*)(pAl + r * 80 + cb + 16);
                al[mf][3] = *(const uint32_t*)(pAl + (r + 8) * 80 + cb + 16);
            }
#pragma unroll
            for (int nf = 0; nf < 8; nf++) {
                const int r = warpN + nf * 8 + g;
                bh[nf][0] = *(const uint32_t*)(pBh + r * 80 + cb);
                bh[nf][1] = *(const uint32_t*)(pBh + r * 80 + cb + 16);
                bl[nf][0] = *(const uint32_t*)(pBl + r * 80 + cb);
                bl[nf][1] = *(const uint32_t*)(pBl + r * 80 + cb + 16);
            }
#pragma unroll
            for (int mf = 0; mf < 2; mf++)
#pragma unroll
                for (int nf = 0; nf < 8; nf++) {
                    MMA_BF16(acc[mf][nf], ah[mf], bh[nf]);
                    MMA_BF16(acc[mf][nf], ah[mf], bl[nf]);
                    MMA_BF16(acc[mf][nf], al[mf], bh[nf]);
                }
        }
    };

    load_stage(0, 0); CP_COMMIT();
    load_stage(1, 1); CP_COMMIT();

    for (int c = 0; c < nchunk; ++c) {
        if (c + 2 < nchunk) { CP_WAIT(1); } else { CP_WAIT(0); }
        __syncthreads();
        if (c + 2 < nchunk) {
            load_stage((c + 2) % NSTAGE, c + 2);
            CP_COMMIT();
        }
        compute_stage(c % NSTAGE);
        __syncthreads();
    }

#pragma unroll
    for (int mf = 0; mf < 2; mf++) {
        const int row0 = bm + warpM + mf * 16 + g;
#pragma unroll
        for (int nf = 0; nf < 8; nf++) {
            const int col = bn + warpN + nf * 8 + tg * 2;
            float2 v0 = make_float2(acc[mf][nf][0], acc[mf][nf][1]);
            float2 v1 = make_float2(acc[mf][nf][2], acc[mf][nf][3]);
            *reinterpret_cast<float2*>(&C[(size_t)row0 * N + col]) = v0;
            *reinterpret_cast<float2*>(&C[(size_t)(row0 + 8) * N + col]) = v1;
        }
    }
}

// ---------------------------------------------------------------------------
// RoPE + scatter -> bf16 hi/lo for Q and K (V handled by vt_kernel)
// Covers qkv cols [0, 2560): 4096 rows x 1280 pairs.
// ---------------------------------------------------------------------------
__global__ void rope_bf16_kernel(const float* __restrict__ qkv,
                                 const float* __restrict__ fc,
                                 __nv_bfloat16* __restrict__ qh, __nv_bfloat16* __restrict__ ql,
                                 __nv_bfloat16* __restrict__ kh, __nv_bfloat16* __restrict__ kl)
{
    const float QSCALE = 0.08838834764831845f;  // 1/sqrt(128)
    size_t idx = (size_t)blockIdx.x * blockDim.x + threadIdx.x;
    if (idx >= (size_t)4096 * 1280) return;
    int m = (int)(idx / 1280);
    int p = (int)(idx - (size_t)m * 1280);
    int n = p * 2;
    int b = m >> 11;
    int s = m & 2047;

    float2 x2 = *reinterpret_cast<const float2*>(&qkv[(size_t)m * 3072 + n]);

    __nv_bfloat16* dh; __nv_bfloat16* dl; size_t addr; float sc;
    int d;
    if (n < 2048) {
        int h = n >> 7; d = n & 127; sc = QSCALE;
        addr = ((size_t)(b * HH + h) * SS + s) * HDD + d;
        dh = qh; dl = ql;
    } else {
        int nn = n - 2048;
        int h = nn >> 7; d = nn & 127; sc = 1.0f;
        addr = ((size_t)(b * KVHH + h) * SS + s) * HDD + d;
        dh = kh; dl = kl;
    }
    float2 cs = *reinterpret_cast<const float2*>(&fc[(size_t)s * 128 + d]);
    float ox = (x2.x * cs.x - x2.y * cs.y) * sc;
    float oy = (x2.x * cs.y + x2.y * cs.x) * sc;
    __nv_bfloat16 hx = __float2bfloat16(ox), hy = __float2bfloat16(oy);
    float lx = ox - __bfloat162float(hx), ly = oy - __bfloat162float(hy);
    uint32_t ph = (uint32_t)__bfloat16_as_ushort(hx) | ((uint32_t)__bfloat16_as_ushort(hy) << 16);
    uint32_t pl = (uint32_t)__bfloat16_as_ushort(__float2bfloat16(lx)) |
                  ((uint32_t)__bfloat16_as_ushort(__float2bfloat16(ly)) << 16);
    *reinterpret_cast<uint32_t*>(dh + addr) = ph;
    *reinterpret_cast<uint32_t*>(dl + addr) = pl;
}

// ---------------------------------------------------------------------------
// V transpose + split: g_qkv V section [b,s][kvh,d] -> Vt hi/lo [b,kvh][d][s]
// grid (64, 4, 8) = (s-tiles, d-tiles, b*kvh); block (32, 8)
// ---------------------------------------------------------------------------
__global__ void vt_kernel(const float* __restrict__ qkv,
                          __nv_bfloat16* __restrict__ vth, __nv_bfloat16* __restrict__ vtl)
{
    __shared__ float t[32][33];
    const int s0 = blockIdx.x * 32, d0 = blockIdx.y * 32;
    const int bk = blockIdx.z;            // b*4 + kvh
    const int b = bk >> 2, kvh = bk & 3;
    const int tx = threadIdx.x, ty = threadIdx.y;
#pragma unroll
    for (int j = 0; j < 4; j++) {
        int s = s0 + ty + j * 8;
        t[ty + j * 8][tx] = qkv[((size_t)(b * 2048 + s)) * 3072 + 2560 + kvh * 128 + d0 + tx];
    }
    __syncthreads();
#pragma unroll
    for (int j = 0; j < 4; j++) {
        int d = d0 + ty + j * 8;
        float v = t[tx][ty + j * 8];
        __nv_bfloat16 h = __float2bfloat16(v);
        size_t o = ((size_t)bk * 128 + d) * 2048 + s0 + tx;
        vth[o] = h;
        vtl[o] = __float2bfloat16(v - __bfloat162float(h));
    }
}

// ---------------------------------------------------------------------------
// Tensor-core flash attention (split-bf16, fp32-equivalent accuracy).
// Grid (32 qblocks reversed, 32 bh), 128 threads (4 warps, m16 rows each).
// BM=BN=64.  K tile rows padded to 272B; Vt rows padded to 144B (both give
// perfectly conflict-free fragment LDS: bank = lane).
// Pipeline: single K buf + single V buf; load V(t) overlaps S(t), load K(t+1)
// overlaps softmax+PV(t).
// ---------------------------------------------------------------------------
#define FT_KH 0
#define FT_KL 17408
#define FT_VH 34816
#define FT_VL 53248
#define FT_SMEM 71680

__global__ __launch_bounds__(128)
void flash_tc_kernel(const __nv_bfloat16* __restrict__ qh_g, const __nv_bfloat16* __restrict__ ql_g,
                     const __nv_bfloat16* __restrict__ kh_g, const __nv_bfloat16* __restrict__ kl_g,
                     const __nv_bfloat16* __restrict__ vth_g, const __nv_bfloat16* __restrict__ vtl_g,
                     __nv_bfloat16* __restrict__ aoh, __nv_bfloat16* __restrict__ aol)
{
    extern __shared__ __align__(16) char smem[];
    const uint32_t sb = s2u(smem);
    const int tid = threadIdx.x, lane = tid & 31, wm = tid >> 5;
    const int g = lane >> 2, tg = lane & 3;
    const int qb = 31 - (int)blockIdx.x;
    const int bh = blockIdx.y;
    const int b = bh >> 4, h = bh & 15, kvh = h >> 2;

    // ---- Q fragments (register-resident for whole CTA) --------------------
    const __nv_bfloat16* qbh = qh_g + ((size_t)(b * HH + h) * SS + qb * 64 + wm * 16) * HDD;
    const __nv_bfloat16* qbl = ql_g + ((size_t)(b * HH + h) * SS + qb * 64 + wm * 16) * HDD;
    uint32_t qfh[8][4], qfl[8][4];
#pragma unroll
    for (int kf = 0; kf < 8; kf++) {
        size_t o0 = (size_t)g * 128 + kf * 16 + tg * 2;
        qfh[kf][0] = *(const uint32_t*)(qbh + o0);
        qfh[kf][1] = *(const uint32_t*)(qbh + o0 + 8 * 128);
        qfh[kf][2] = *(const uint32_t*)(qbh + o0 + 8);
        qfh[kf][3] = *(const uint32_t*)(qbh + o0 + 8 * 128 + 8);
        qfl[kf][0] = *(const uint32_t*)(qbl + o0);
        qfl[kf][1] = *(const uint32_t*)(qbl + o0 + 8 * 128);
        qfl[kf][2] = *(const uint32_t*)(qbl + o0 + 8);
        qfl[kf][3] = *(const uint32_t*)(qbl + o0 + 8 * 128 + 8);
    }

    const size_t kvbase = (size_t)(b * KVHH + kvh) * SS * HDD;

    auto load_K = [&](int kt) {
        const char* sh = (const char*)(kh_g + kvbase + (size_t)kt * 64 * 128);
        const char* sl = (const char*)(kl_g + kvbase + (size_t)kt * 64 * 128);
#pragma unroll
        for (int i = 0; i < 8; i++) {
            int c = tid + i * 128;
            int key = c >> 4, q = c & 15;
            CP_ASYNC16(sb + FT_KH + key * 272 + q * 16, sh + key * 256 + q * 16);
            CP_ASYNC16(sb + FT_KL + key * 272 + q * 16, sl + key * 256 + q * 16);
        }
    };
    auto load_V = [&](int kt) {
        const size_t vb = (size_t)(b * KVHH + kvh) * HDD * SS + (size_t)kt * 64;
#pragma unroll
        for (int i = 0; i < 8; i++) {
            int c = tid + i * 128;
            int d = c >> 3, q = c & 7;
            const char* sh = (const char*)(vth_g + vb + (size_t)d * 2048) + q * 16;
            const char* sl = (const char*)(vtl_g + vb + (size_t)d * 2048) + q * 16;
            CP_ASYNC16(sb + FT_VH + d * 144 + q * 16, sh);
            CP_ASYNC16(sb + FT_VL + d * 144 + q * 16, sl);
        }
    };

    float of[16][4];
#pragma unroll
    for (int i = 0; i < 16; i++)
#pragma unroll
        for (int r = 0; r < 4; r++) of[i][r] = 0.0f;
    float m0 = -1e30f, m1 = -1e30f, l0 = 0.0f, l1 = 0.0f;

    const int nt = qb + 1;
    load_K(0); CP_COMMIT();

    for (int kt = 0; kt < nt; kt++) {
        CP_WAIT(0);                 // K(kt) landed
        __syncthreads();            // ... in all threads; V buf free (prev PV done)
        load_V(kt); CP_COMMIT();    // overlaps S compute

        // ---- S = Q K^T (3-term split) ------------------------------------
        float sacc[8][4];
#pragma unroll
        for (int nf = 0; nf < 8; nf++)
#pragma unroll
            for (int r = 0; r < 4; r++) sacc[nf][r] = 0.0f;

#pragma unroll
        for (int kf = 0; kf < 8; kf++) {
#pragma unroll
            for (int nf = 0; nf < 8; nf++) {
                const int ko = FT_KH + (nf * 8 + g) * 272 + kf * 32 + tg * 4;
                uint32_t bhf[2], blf[2];
                bhf[0] = *(const uint32_t*)(smem + ko);
                bhf[1] = *(const uint32_t*)(smem + ko + 16);
                blf[0] = *(const uint32_t*)(smem + ko + (FT_KL - FT_KH));
                blf[1] = *(const uint32_t*)(smem + ko + (FT_KL - FT_KH) + 16);
                MMA_BF16(sacc[nf], qfh[kf], bhf);
                MMA_BF16(sacc[nf], qfh[kf], blf);
                MMA_BF16(sacc[nf], qfl[kf], bhf);
            }
        }

        CP_WAIT(0);                 // V(kt) landed
        __syncthreads();            // all warps done reading K buf
        if (kt + 1 < nt) { load_K(kt + 1); CP_COMMIT(); }  // overlaps softmax+PV

        // ---- causal mask on diagonal tile --------------------------------
        if (kt == qb) {
            const int r0 = wm * 16 + g, r1 = r0 + 8;
#pragma unroll
            for (int nf = 0; nf < 8; nf++) {
                const int c0 = nf * 8 + tg * 2;
                if (c0     > r0) sacc[nf][0] = -1e30f;
                if (c0 + 1 > r0) sacc[nf][1] = -1e30f;
                if (c0     > r1) sacc[nf][2] = -1e30f;
                if (c0 + 1 > r1) sacc[nf][3] = -1e30f;
            }
        }

        // ---- online softmax; build P fragments in registers --------------
        float mx0 = -1e30f, mx1 = -1e30f;
#pragma unroll
        for (int nf = 0; nf < 8; nf++) {
            mx0 = fmaxf(mx0, fmaxf(sacc[nf][0], sacc[nf][1]));
            mx1 = fmaxf(mx1, fmaxf(sacc[nf][2], sacc[nf][3]));
        }
        mx0 = fmaxf(mx0, __shfl_xor_sync(0xffffffffu, mx0, 1));
        mx0 = fmaxf(mx0, __shfl_xor_sync(0xffffffffu, mx0, 2));
        mx1 = fmaxf(mx1, __shfl_xor_sync(0xffffffffu, mx1, 1));
        mx1 = fmaxf(mx1, __shfl_xor_sync(0xffffffffu, mx1, 2));
        const float mn0 = fmaxf(m0, mx0), mn1 = fmaxf(m1, mx1);
        const float al0 = __expf(m0 - mn0), al1 = __expf(m1 - mn1);

        uint32_t paH[4][4], paL[4][4];
        float rs0 = 0.0f, rs1 = 0.0f;
#pragma unroll
        for (int nf = 0; nf < 8; nf++) {
            float p0 = __expf(sacc[nf][0] - mn0);
            float p1 = __expf(sacc[nf][1] - mn0);
            float p2 = __expf(sacc[nf][2] - mn1);
            float p3 = __expf(sacc[nf][3] - mn1);
            rs0 += p0 + p1;
            rs1 += p2 + p3;
            __nv_bfloat16 h0 = __float2bfloat16(p0), h1 = __float2bfloat16(p1);
            __nv_bfloat16 h2 = __float2bfloat16(p2), h3 = __float2bfloat16(p3);
            const int kfp = nf >> 1, o = (nf & 1) * 2;
            paH[kfp][o]     = (uint32_t)__bfloat16_as_ushort(h0) |
                              ((uint32_t)__bfloat16_as_ushort(h1) << 16);
            paH[kfp][o + 1] = (uint32_t)__bfloat16_as_ushort(h2) |
                              ((uint32_t)__bfloat16_as_ushort(h3) << 16);
            paL[kfp][o]     = pack_bf16(p0 - __bfloat162float(h0), p1 - __bfloat162float(h1));
            paL[kfp][o + 1] = pack_bf16(p2 - __bfloat162float(h2), p3 - __bfloat162float(h3));
        }
        rs0 += __shfl_xor_sync(0xffffffffu, rs0, 1);
        rs0 += __shfl_xor_sync(0xffffffffu, rs0, 2);
        rs1 += __shfl_xor_sync(0xffffffffu, rs1, 1);
        rs1 += __shfl_xor_sync(0xffffffffu, rs1, 2);
        l0 = l0 * al0 + rs0;
        l1 = l1 * al1 + rs1;
        m0 = mn0; m1 = mn1;
#pragma unroll
        for (int nfo = 0; nfo < 16; nfo++) {
            of[nfo][0] *= al0; of[nfo][1] *= al0;
            of[nfo][2] *= al1; of[nfo][3] *= al1;
        }

        // ---- O += P V (3-term split) -------------------------------------
#pragma unroll
        for (int kfp = 0; kfp < 4; kfp++) {
#pragma unroll
            for (int nfo = 0; nfo < 16; nfo++) {
                const int vo = FT_VH + (nfo * 8 + g) * 144 + kfp * 32 + tg * 4;
                uint32_t vh[2], vl[2];
                vh[0] = *(const uint32_t*)(smem + vo);
                vh[1] = *(const uint32_t*)(smem + vo + 16);
                vl[0] = *(const uint32_t*)(smem + vo + (FT_VL - FT_VH));
                vl[1] = *(const uint32_t*)(smem + vo + (FT_VL - FT_VH) + 16);
                MMA_BF16(of[nfo], paH[kfp], vh);
                MMA_BF16(of[nfo], paH[kfp], vl);
                MMA_BF16(of[nfo], paL[kfp], vh);
            }
        }
    }

    // ---- epilogue: normalize, split to bf16 hi/lo, write [b*S+row][h*128+col]
    const float inv0 = 1.0f / l0, inv1 = 1.0f / l1;
    const int row0 = b * SS + qb * 64 + wm * 16 + g;
    const size_t base0 = (size_t)row0 * (HH * HDD) + (size_t)h * HDD;
    const size_t base1 = base0 + (size_t)8 * (HH * HDD);
#pragma unroll
    for (int nfo = 0; nfo < 16; nfo++) {
        const int col = nfo * 8 + tg * 2;
        float o0 = of[nfo][0] * inv0, o1 = of[nfo][1] * inv0;
        float o2 = of[nfo][2] * inv1, o3 = of[nfo][3] * inv1;
        __nv_bfloat16 h0 = __float2bfloat16(o0), h1 = __float2bfloat16(o1);
        __nv_bfloat16 h2 = __float2bfloat16(o2), h3 = __float2bfloat16(o3);
        *reinterpret_cast<uint32_t*>(aoh + base0 + col) =
            (uint32_t)__bfloat16_as_ushort(h0) | ((uint32_t)__bfloat16_as_ushort(h1) << 16);
        *reinterpret_cast<uint32_t*>(aol + base0 + col) =
            pack_bf16(o0 - __bfloat162float(h0), o1 - __bfloat162float(h1));
        *reinterpret_cast<uint32_t*>(aoh + base1 + col) =
            (uint32_t)__bfloat16_as_ushort(h2) | ((uint32_t)__bfloat16_as_ushort(h3) << 16);
        *reinterpret_cast<uint32_t*>(aol + base1 + col) =
            pack_bf16(o2 - __bfloat162float(h2), o3 - __bfloat162float(h3));
    }
}

// ---------------------------------------------------------------------------
// Host launcher
// ---------------------------------------------------------------------------
extern "C" void kernel_launch(void* const* d_in, const int* in_sizes, int n_in,
                              void* d_out, int out_size)
{
    (void)in_sizes; (void)n_in; (void)out_size;
    const float* x  = (const float*)d_in[0];
    const float* fc = (const float*)d_in[1];
    const float* wq = (const float*)d_in[2];
    const float* wk = (const float*)d_in[3];
    const float* wv = (const float*)d_in[4];
    const float* wo = (const float*)d_in[5];
    float* out = (float*)d_out;

    float* pqkv;
    __nv_bfloat16 *pxh, *pxl, *pwh, *pwl, *paoh, *paol, *pwoh, *pwol;
    __nv_bfloat16 *pqh, *pql, *pkh, *pkl, *pvth, *pvtl;
    cudaGetSymbolAddress((void**)&pqkv,  g_qkv);
    cudaGetSymbolAddress((void**)&pxh,   g_x_h);
    cudaGetSymbolAddress((void**)&pxl,   g_x_l);
    cudaGetSymbolAddress((void**)&pwh,   g_w_h);
    cudaGetSymbolAddress((void**)&pwl,   g_w_l);
    cudaGetSymbolAddress((void**)&paoh,  g_ao_h);
    cudaGetSymbolAddress((void**)&paol,  g_ao_l);
    cudaGetSymbolAddress((void**)&pwoh,  g_wo_h);
    cudaGetSymbolAddress((void**)&pwol,  g_wo_l);
    cudaGetSymbolAddress((void**)&pqh,   g_qh);
    cudaGetSymbolAddress((void**)&pql,   g_ql);
    cudaGetSymbolAddress((void**)&pkh,   g_kh);
    cudaGetSymbolAddress((void**)&pkl,   g_kl);
    cudaGetSymbolAddress((void**)&pvth,  g_vth);
    cudaGetSymbolAddress((void**)&pvtl,  g_vtl);

    cudaFuncSetAttribute(tc_gemm_kernel, cudaFuncAttributeMaxDynamicSharedMemorySize, GEMM_SMEM);
    cudaFuncSetAttribute(flash_tc_kernel, cudaFuncAttributeMaxDynamicSharedMemorySize, FT_SMEM);

    // Split-convert inputs
    {
        long n4 = (long)4096 * 2048 / 4;
        cvt_split_kernel<<<(unsigned)((n4 + 255) / 256), 256>>>(x, pxh, pxl, n4);
    }
    {
        long n4 = (long)2048 * 2048 / 4;
        cvt_split_kernel<<<(unsigned)((n4 + 255) / 256), 256>>>(wq, pwh, pwl, n4);
    }
    {
        long n4 = (long)512 * 2048 / 4;
        size_t off = (size_t)2048 * 2048;
        cvt_split_kernel<<<(unsigned)((n4 + 255) / 256), 256>>>(wk, pwh + off, pwl + off, n4);
        size_t off2 = (size_t)2560 * 2048;
        cvt_split_kernel<<<(unsigned)((n4 + 255) / 256), 256>>>(wv, pwh + off2, pwl + off2, n4);
    }

    // QKV projection: [4096,2048] x [3072,2048]^T -> [4096,3072]
    tc_gemm_kernel<<<dim3(3072 / GBN, 4096 / GBM), 256, GEMM_SMEM>>>(
        pxh, pxl, pwh, pwl, pqkv, 3072, 2048);

    // RoPE -> Q/K bf16 hi/lo; V transpose -> Vt bf16 hi/lo
    rope_bf16_kernel<<<20480, 256>>>(pqkv, fc, pqh, pql, pkh, pkl);
    vt_kernel<<<dim3(64, 4, 8), dim3(32, 8)>>>(pqkv, pvth, pvtl);

    // Tensor-core flash attention -> ao hi/lo
    flash_tc_kernel<<<dim3(32, 32), 128, FT_SMEM>>>(pqh, pql, pkh, pkl, pvth, pvtl, paoh, paol);

    // wo projection: [4096,2048] x [2048,2048]^T -> out
    {
        long n4 = (long)2048 * 2048 / 4;
        cvt_split_kernel<<<(unsigned)((n4 + 255) / 256), 256>>>(wo, pwoh, pwol, n4);
    }
    tc_gemm_kernel<<<dim3(2048 / GBN, 4096 / GBM), 256, GEMM_SMEM>>>(
        paoh, paol, pwoh, pwol, out, 2048, 2048);
}

// round 11
// speedup vs baseline: 4.0553x; 1.7716x over previous
#include <cuda_runtime.h>
#include <cuda_bf16.h>
#include <cuda_fp16.h>
#include <cstdint>
#include <cstddef>

// Problem constants
#define BB   2
#define SS   2048
#define DIMM 2048
#define HH   16
#define KVHH 4
#define HDD  128
// M = B*S = 4096, QKV N = 3072, K = 2048

// ---------------------------------------------------------------------------
// Scratch (static device globals; no allocation anywhere)
// ---------------------------------------------------------------------------
__device__ float  g_qkv[(size_t)4096 * 3072];           // qkv = x @ Wqkv^T
__device__ __half g_xh [(size_t)4096 * 2048];           // x fp16
__device__ __half g_wh [(size_t)3072 * 2048];           // concat [wq;wk;wv] fp16
__device__ __half g_ao [(size_t)4096 * 2048];           // attn out fp16 (flash writes)
__device__ __half g_woh[(size_t)2048 * 2048];           // wo fp16

// flash operands, bf16 hi/lo (split kept for accuracy hedge)
__device__ __nv_bfloat16 g_qh [(size_t)BB * HH  * SS * HDD];  // [b][h][s][hd] roped+scaled
__device__ __nv_bfloat16 g_ql [(size_t)BB * HH  * SS * HDD];
__device__ __nv_bfloat16 g_kh [(size_t)BB * KVHH * SS * HDD]; // [b][kvh][s][hd] roped
__device__ __nv_bfloat16 g_kl [(size_t)BB * KVHH * SS * HDD];
__device__ __nv_bfloat16 g_vth[(size_t)BB * KVHH * HDD * SS]; // [b][kvh][hd][s]
__device__ __nv_bfloat16 g_vtl[(size_t)BB * KVHH * HDD * SS];

// ---------------------------------------------------------------------------
// PTX helpers (sm_80+ baseline: cp.async + mma.sync)
// ---------------------------------------------------------------------------
__device__ __forceinline__ uint32_t s2u(const void* p) {
    uint32_t a;
    asm("{ .reg .u64 t; cvta.to.shared.u64 t, %1; cvt.u32.u64 %0, t; }" : "=r"(a) : "l"(p));
    return a;
}

#define CP_ASYNC16(dst, src) \
    asm volatile("cp.async.cg.shared.global [%0], [%1], 16;" :: "r"(dst), "l"(src) : "memory")
#define CP_COMMIT() asm volatile("cp.async.commit_group;" ::: "memory")
#define CP_WAIT(n)  asm volatile("cp.async.wait_group %0;" :: "n"(n) : "memory")

// D += A * B  (m16n8k16, row.col, bf16 in, fp32 acc)
#define MMA_BF16(acc, a, b) \
    asm volatile("mma.sync.aligned.m16n8k16.row.col.f32.bf16.bf16.f32 " \
                 "{%0,%1,%2,%3}, {%4,%5,%6,%7}, {%8,%9}, {%0,%1,%2,%3};" \
                 : "+f"((acc)[0]), "+f"((acc)[1]), "+f"((acc)[2]), "+f"((acc)[3]) \
                 : "r"((a)[0]), "r"((a)[1]), "r"((a)[2]), "r"((a)[3]), \
                   "r"((b)[0]), "r"((b)[1]))

// D += A * B  (m16n8k16, row.col, fp16 in, fp32 acc)
#define MMA_F16(acc, a, b) \
    asm volatile("mma.sync.aligned.m16n8k16.row.col.f32.f16.f16.f32 " \
                 "{%0,%1,%2,%3}, {%4,%5,%6,%7}, {%8,%9}, {%0,%1,%2,%3};" \
                 : "+f"((acc)[0]), "+f"((acc)[1]), "+f"((acc)[2]), "+f"((acc)[3]) \
                 : "r"((a)[0]), "r"((a)[1]), "r"((a)[2]), "r"((a)[3]), \
                   "r"((b)[0]), "r"((b)[1]))

__device__ __forceinline__ uint32_t pack_bf16(float a, float b) {
    uint32_t lo = __bfloat16_as_ushort(__float2bfloat16(a));
    uint32_t hi = __bfloat16_as_ushort(__float2bfloat16(b));
    return lo | (hi << 16);
}
__device__ __forceinline__ uint32_t pack_h(float a, float b) {
    __half2 h = __floats2half2_rn(a, b);
    return *reinterpret_cast<uint32_t*>(&h);
}

// ---------------------------------------------------------------------------
// fp32 -> fp16 convert (float4 per thread)
// ---------------------------------------------------------------------------
__global__ void cvt_h_kernel(const float* __restrict__ src, __half* __restrict__ dst, long n4)
{
    long i = (long)blockIdx.x * blockDim.x + threadIdx.x;
    if (i >= n4) return;
    float4 v = reinterpret_cast<const float4*>(src)[i];
    uint2 o;
    o.x = pack_h(v.x, v.y);
    o.y = pack_h(v.z, v.w);
    *reinterpret_cast<uint2*>(dst + i * 4) = o;
}

// ---------------------------------------------------------------------------
// mma.sync fp16 GEMM: C[M,N] = A[M,K] * B[N,K]^T  (fp16 in, fp32 acc)
// Tile 128x128, BK=32, 3-stage cp.async pipeline, 256 threads (8 warps 4x2,
// warp tile 32x64). smem rows padded to 80 B -> conflict-free LDS.
// ---------------------------------------------------------------------------
#define GBM 128
#define GBN 128
#define GBK 32
#define TILE_BYTES  (128 * 80)
#define STAGE_BYTES (2 * TILE_BYTES)        // A | B
#define NSTAGE 3
#define GEMM_SMEM (NSTAGE * STAGE_BYTES)    // 61440 B

__global__ __launch_bounds__(256)
void tc_gemm_f16_kernel(const __half* __restrict__ A, const __half* __restrict__ B,
                        float* __restrict__ C, int N, int K)
{
    extern __shared__ __align__(16) char smem[];
    const uint32_t smem_u = s2u(smem);
    const int tid  = threadIdx.x;
    const int lane = tid & 31;
    const int wid  = tid >> 5;
    const int g  = lane >> 2;
    const int tg = lane & 3;
    const int warpM = (wid >> 1) * 32;
    const int warpN = (wid & 1) * 64;
    const int bm = blockIdx.y * GBM;
    const int bn = blockIdx.x * GBN;
    const int nchunk = K / GBK;

    float acc[2][8][4];
#pragma unroll
    for (int mf = 0; mf < 2; mf++)
#pragma unroll
        for (int nf = 0; nf < 8; nf++)
#pragma unroll
            for (int r = 0; r < 4; r++) acc[mf][nf][r] = 0.0f;

    auto load_stage = [&](int s, int c) {
        const int k0 = c * GBK;
        const uint32_t stg = smem_u + (uint32_t)s * STAGE_BYTES;
#pragma unroll
        for (int i = 0; i < 4; i++) {
            int f = tid + i * 256;            // 0..1023
            int tile = f >> 9;                // 0:A 1:B
            int fi = f & 511;
            int r = fi >> 2, q = fi & 3;
            const __half* src = (tile == 0) ? A + (size_t)(bm + r) * K + k0 + q * 8
                                            : B + (size_t)(bn + r) * K + k0 + q * 8;
            uint32_t dst = stg + (uint32_t)tile * TILE_BYTES + (uint32_t)r * 80 + q * 16;
            CP_ASYNC16(dst, src);
        }
    };

    auto compute_stage = [&](int s) {
        const char* stg = smem + (size_t)s * STAGE_BYTES;
        const char* pA = stg;
        const char* pB = stg + TILE_BYTES;
#pragma unroll
        for (int ks = 0; ks < 2; ks++) {
            const int cb = (ks * 16 + tg * 2) * 2;
            uint32_t a[2][4], b[8][2];
#pragma unroll
            for (int mf = 0; mf < 2; mf++) {
                const int r = warpM + mf * 16 + g;
                a[mf][0] = *(const uint32_t*)(pA + r * 80 + cb);
                a[mf][1] = *(const uint32_t*)(pA + (r + 8) * 80 + cb);
                a[mf][2] = *(const uint32_t*)(pA + r * 80 + cb + 16);
                a[mf][3] = *(const uint32_t*)(pA + (r + 8) * 80 + cb + 16);
            }
#pragma unroll
            for (int nf = 0; nf < 8; nf++) {
                const int r = warpN + nf * 8 + g;
                b[nf][0] = *(const uint32_t*)(pB + r * 80 + cb);
                b[nf][1] = *(const uint32_t*)(pB + r * 80 + cb + 16);
            }
#pragma unroll
            for (int mf = 0; mf < 2; mf++)
#pragma unroll
                for (int nf = 0; nf < 8; nf++)
                    MMA_F16(acc[mf][nf], a[mf], b[nf]);
        }
    };

    load_stage(0, 0); CP_COMMIT();
    load_stage(1, 1); CP_COMMIT();

    for (int c = 0; c < nchunk; ++c) {
        if (c + 2 < nchunk) { CP_WAIT(1); } else { CP_WAIT(0); }
        __syncthreads();
        if (c + 2 < nchunk) {
            load_stage((c + 2) % NSTAGE, c + 2);
            CP_COMMIT();
        }
        compute_stage(c % NSTAGE);
        __syncthreads();
    }

#pragma unroll
    for (int mf = 0; mf < 2; mf++) {
        const int row0 = bm + warpM + mf * 16 + g;
#pragma unroll
        for (int nf = 0; nf < 8; nf++) {
            const int col = bn + warpN + nf * 8 + tg * 2;
            float2 v0 = make_float2(acc[mf][nf][0], acc[mf][nf][1]);
            float2 v1 = make_float2(acc[mf][nf][2], acc[mf][nf][3]);
            *reinterpret_cast<float2*>(&C[(size_t)row0 * N + col]) = v0;
            *reinterpret_cast<float2*>(&C[(size_t)(row0 + 8) * N + col]) = v1;
        }
    }
}

// ---------------------------------------------------------------------------
// RoPE + scatter -> bf16 hi/lo for Q and K (V handled by vt_kernel)
// ---------------------------------------------------------------------------
__global__ void rope_bf16_kernel(const float* __restrict__ qkv,
                                 const float* __restrict__ fc,
                                 __nv_bfloat16* __restrict__ qh, __nv_bfloat16* __restrict__ ql,
                                 __nv_bfloat16* __restrict__ kh, __nv_bfloat16* __restrict__ kl)
{
    const float QSCALE = 0.08838834764831845f;  // 1/sqrt(128)
    size_t idx = (size_t)blockIdx.x * blockDim.x + threadIdx.x;
    if (idx >= (size_t)4096 * 1280) return;
    int m = (int)(idx / 1280);
    int p = (int)(idx - (size_t)m * 1280);
    int n = p * 2;
    int b = m >> 11;
    int s = m & 2047;

    float2 x2 = *reinterpret_cast<const float2*>(&qkv[(size_t)m * 3072 + n]);

    __nv_bfloat16* dh; __nv_bfloat16* dl; size_t addr; float sc;
    int d;
    if (n < 2048) {
        int h = n >> 7; d = n & 127; sc = QSCALE;
        addr = ((size_t)(b * HH + h) * SS + s) * HDD + d;
        dh = qh; dl = ql;
    } else {
        int nn = n - 2048;
        int h = nn >> 7; d = nn & 127; sc = 1.0f;
        addr = ((size_t)(b * KVHH + h) * SS + s) * HDD + d;
        dh = kh; dl = kl;
    }
    float2 cs = *reinterpret_cast<const float2*>(&fc[(size_t)s * 128 + d]);
    float ox = (x2.x * cs.x - x2.y * cs.y) * sc;
    float oy = (x2.x * cs.y + x2.y * cs.x) * sc;
    __nv_bfloat16 hx = __float2bfloat16(ox), hy = __float2bfloat16(oy);
    float lx = ox - __bfloat162float(hx), ly = oy - __bfloat162float(hy);
    uint32_t ph = (uint32_t)__bfloat16_as_ushort(hx) | ((uint32_t)__bfloat16_as_ushort(hy) << 16);
    uint32_t pl = (uint32_t)__bfloat16_as_ushort(__float2bfloat16(lx)) |
                  ((uint32_t)__bfloat16_as_ushort(__float2bfloat16(ly)) << 16);
    *reinterpret_cast<uint32_t*>(dh + addr) = ph;
    *reinterpret_cast<uint32_t*>(dl + addr) = pl;
}

// ---------------------------------------------------------------------------
// V transpose + split: g_qkv V section [b,s][kvh,d] -> Vt hi/lo [b,kvh][d][s]
// ---------------------------------------------------------------------------
__global__ void vt_kernel(const float* __restrict__ qkv,
                          __nv_bfloat16* __restrict__ vth, __nv_bfloat16* __restrict__ vtl)
{
    __shared__ float t[32][33];
    const int s0 = blockIdx.x * 32, d0 = blockIdx.y * 32;
    const int bk = blockIdx.z;            // b*4 + kvh
    const int b = bk >> 2, kvh = bk & 3;
    const int tx = threadIdx.x, ty = threadIdx.y;
#pragma unroll
    for (int j = 0; j < 4; j++) {
        int s = s0 + ty + j * 8;
        t[ty + j * 8][tx] = qkv[((size_t)(b * 2048 + s)) * 3072 + 2560 + kvh * 128 + d0 + tx];
    }
    __syncthreads();
#pragma unroll
    for (int j = 0; j < 4; j++) {
        int d = d0 + ty + j * 8;
        float v = t[tx][ty + j * 8];
        __nv_bfloat16 h = __float2bfloat16(v);
        size_t o = ((size_t)bk * 128 + d) * 2048 + s0 + tx;
        vth[o] = h;
        vtl[o] = __float2bfloat16(v - __bfloat162float(h));
    }
}

// ---------------------------------------------------------------------------
// Tensor-core flash attention (split-bf16).  Epilogue writes fp16 attn out.
// ---------------------------------------------------------------------------
#define FT_KH 0
#define FT_KL 17408
#define FT_VH 34816
#define FT_VL 53248
#define FT_SMEM 71680

__global__ __launch_bounds__(128)
void flash_tc_kernel(const __nv_bfloat16* __restrict__ qh_g, const __nv_bfloat16* __restrict__ ql_g,
                     const __nv_bfloat16* __restrict__ kh_g, const __nv_bfloat16* __restrict__ kl_g,
                     const __nv_bfloat16* __restrict__ vth_g, const __nv_bfloat16* __restrict__ vtl_g,
                     __half* __restrict__ ao)
{
    extern __shared__ __align__(16) char smem[];
    const uint32_t sb = s2u(smem);
    const int tid = threadIdx.x, lane = tid & 31, wm = tid >> 5;
    const int g = lane >> 2, tg = lane & 3;
    const int qb = 31 - (int)blockIdx.x;
    const int bh = blockIdx.y;
    const int b = bh >> 4, h = bh & 15, kvh = h >> 2;

    const __nv_bfloat16* qbh = qh_g + ((size_t)(b * HH + h) * SS + qb * 64 + wm * 16) * HDD;
    const __nv_bfloat16* qbl = ql_g + ((size_t)(b * HH + h) * SS + qb * 64 + wm * 16) * HDD;
    uint32_t qfh[8][4], qfl[8][4];
#pragma unroll
    for (int kf = 0; kf < 8; kf++) {
        size_t o0 = (size_t)g * 128 + kf * 16 + tg * 2;
        qfh[kf][0] = *(const uint32_t*)(qbh + o0);
        qfh[kf][1] = *(const uint32_t*)(qbh + o0 + 8 * 128);
        qfh[kf][2] = *(const uint32_t*)(qbh + o0 + 8);
        qfh[kf][3] = *(const uint32_t*)(qbh + o0 + 8 * 128 + 8);
        qfl[kf][0] = *(const uint32_t*)(qbl + o0);
        qfl[kf][1] = *(const uint32_t*)(qbl + o0 + 8 * 128);
        qfl[kf][2] = *(const uint32_t*)(qbl + o0 + 8);
        qfl[kf][3] = *(const uint32_t*)(qbl + o0 + 8 * 128 + 8);
    }

    const size_t kvbase = (size_t)(b * KVHH + kvh) * SS * HDD;

    auto load_K = [&](int kt) {
        const char* sh = (const char*)(kh_g + kvbase + (size_t)kt * 64 * 128);
        const char* sl = (const char*)(kl_g + kvbase + (size_t)kt * 64 * 128);
#pragma unroll
        for (int i = 0; i < 8; i++) {
            int c = tid + i * 128;
            int key = c >> 4, q = c & 15;
            CP_ASYNC16(sb + FT_KH + key * 272 + q * 16, sh + key * 256 + q * 16);
            CP_ASYNC16(sb + FT_KL + key * 272 + q * 16, sl + key * 256 + q * 16);
        }
    };
    auto load_V = [&](int kt) {
        const size_t vb = (size_t)(b * KVHH + kvh) * HDD * SS + (size_t)kt * 64;
#pragma unroll
        for (int i = 0; i < 8; i++) {
            int c = tid + i * 128;
            int d = c >> 3, q = c & 7;
            const char* sh = (const char*)(vth_g + vb + (size_t)d * 2048) + q * 16;
            const char* sl = (const char*)(vtl_g + vb + (size_t)d * 2048) + q * 16;
            CP_ASYNC16(sb + FT_VH + d * 144 + q * 16, sh);
            CP_ASYNC16(sb + FT_VL + d * 144 + q * 16, sl);
        }
    };

    float of[16][4];
#pragma unroll
    for (int i = 0; i < 16; i++)
#pragma unroll
        for (int r = 0; r < 4; r++) of[i][r] = 0.0f;
    float m0 = -1e30f, m1 = -1e30f, l0 = 0.0f, l1 = 0.0f;

    const int nt = qb + 1;
    load_K(0); CP_COMMIT();

    for (int kt = 0; kt < nt; kt++) {
        CP_WAIT(0);
        __syncthreads();
        load_V(kt); CP_COMMIT();

        float sacc[8][4];
#pragma unroll
        for (int nf = 0; nf < 8; nf++)
#pragma unroll
            for (int r = 0; r < 4; r++) sacc[nf][r] = 0.0f;

#pragma unroll
        for (int kf = 0; kf < 8; kf++) {
#pragma unroll
            for (int nf = 0; nf < 8; nf++) {
                const int ko = FT_KH + (nf * 8 + g) * 272 + kf * 32 + tg * 4;
                uint32_t bhf[2], blf[2];
                bhf[0] = *(const uint32_t*)(smem + ko);
                bhf[1] = *(const uint32_t*)(smem + ko + 16);
                blf[0] = *(const uint32_t*)(smem + ko + (FT_KL - FT_KH));
                blf[1] = *(const uint32_t*)(smem + ko + (FT_KL - FT_KH) + 16);
                MMA_BF16(sacc[nf], qfh[kf], bhf);
                MMA_BF16(sacc[nf], qfh[kf], blf);
                MMA_BF16(sacc[nf], qfl[kf], bhf);
            }
        }

        CP_WAIT(0);
        __syncthreads();
        if (kt + 1 < nt) { load_K(kt + 1); CP_COMMIT(); }

        if (kt == qb) {
            const int r0 = wm * 16 + g, r1 = r0 + 8;
#pragma unroll
            for (int nf = 0; nf < 8; nf++) {
                const int c0 = nf * 8 + tg * 2;
                if (c0     > r0) sacc[nf][0] = -1e30f;
                if (c0 + 1 > r0) sacc[nf][1] = -1e30f;
                if (c0     > r1) sacc[nf][2] = -1e30f;
                if (c0 + 1 > r1) sacc[nf][3] = -1e30f;
            }
        }

        float mx0 = -1e30f, mx1 = -1e30f;
#pragma unroll
        for (int nf = 0; nf < 8; nf++) {
            mx0 = fmaxf(mx0, fmaxf(sacc[nf][0], sacc[nf][1]));
            mx1 = fmaxf(mx1, fmaxf(sacc[nf][2], sacc[nf][3]));
        }
        mx0 = fmaxf(mx0, __shfl_xor_sync(0xffffffffu, mx0, 1));
        mx0 = fmaxf(mx0, __shfl_xor_sync(0xffffffffu, mx0, 2));
        mx1 = fmaxf(mx1, __shfl_xor_sync(0xffffffffu, mx1, 1));
        mx1 = fmaxf(mx1, __shfl_xor_sync(0xffffffffu, mx1, 2));
        const float mn0 = fmaxf(m0, mx0), mn1 = fmaxf(m1, mx1);
        const float al0 = __expf(m0 - mn0), al1 = __expf(m1 - mn1);

        uint32_t paH[4][4], paL[4][4];
        float rs0 = 0.0f, rs1 = 0.0f;
#pragma unroll
        for (int nf = 0; nf < 8; nf++) {
            float p0 = __expf(sacc[nf][0] - mn0);
            float p1 = __expf(sacc[nf][1] - mn0);
            float p2 = __expf(sacc[nf][2] - mn1);
            float p3 = __expf(sacc[nf][3] - mn1);
            rs0 += p0 + p1;
            rs1 += p2 + p3;
            __nv_bfloat16 h0 = __float2bfloat16(p0), h1 = __float2bfloat16(p1);
            __nv_bfloat16 h2 = __float2bfloat16(p2), h3 = __float2bfloat16(p3);
            const int kfp = nf >> 1, o = (nf & 1) * 2;
            paH[kfp][o]     = (uint32_t)__bfloat16_as_ushort(h0) |
                              ((uint32_t)__bfloat16_as_ushort(h1) << 16);
            paH[kfp][o + 1] = (uint32_t)__bfloat16_as_ushort(h2) |
                              ((uint32_t)__bfloat16_as_ushort(h3) << 16);
            paL[kfp][o]     = pack_bf16(p0 - __bfloat162float(h0), p1 - __bfloat162float(h1));
            paL[kfp][o + 1] = pack_bf16(p2 - __bfloat162float(h2), p3 - __bfloat162float(h3));
        }
        rs0 += __shfl_xor_sync(0xffffffffu, rs0, 1);
        rs0 += __shfl_xor_sync(0xffffffffu, rs0, 2);
        rs1 += __shfl_xor_sync(0xffffffffu, rs1, 1);
        rs1 += __shfl_xor_sync(0xffffffffu, rs1, 2);
        l0 = l0 * al0 + rs0;
        l1 = l1 * al1 + rs1;
        m0 = mn0; m1 = mn1;
#pragma unroll
        for (int nfo = 0; nfo < 16; nfo++) {
            of[nfo][0] *= al0; of[nfo][1] *= al0;
            of[nfo][2] *= al1; of[nfo][3] *= al1;
        }

#pragma unroll
        for (int kfp = 0; kfp < 4; kfp++) {
#pragma unroll
            for (int nfo = 0; nfo < 16; nfo++) {
                const int vo = FT_VH + (nfo * 8 + g) * 144 + kfp * 32 + tg * 4;
                uint32_t vh[2], vl[2];
                vh[0] = *(const uint32_t*)(smem + vo);
                vh[1] = *(const uint32_t*)(smem + vo + 16);
                vl[0] = *(const uint32_t*)(smem + vo + (FT_VL - FT_VH));
                vl[1] = *(const uint32_t*)(smem + vo + (FT_VL - FT_VH) + 16);
                MMA_BF16(of[nfo], paH[kfp], vh);
                MMA_BF16(of[nfo], paH[kfp], vl);
                MMA_BF16(of[nfo], paL[kfp], vh);
            }
        }
    }

    // ---- epilogue: normalize, write fp16 attn out [b*S+row][h*128+col] ----
    const float inv0 = 1.0f / l0, inv1 = 1.0f / l1;
    const int row0 = b * SS + qb * 64 + wm * 16 + g;
    const size_t base0 = (size_t)row0 * (HH * HDD) + (size_t)h * HDD;
    const size_t base1 = base0 + (size_t)8 * (HH * HDD);
#pragma unroll
    for (int nfo = 0; nfo < 16; nfo++) {
        const int col = nfo * 8 + tg * 2;
        *reinterpret_cast<uint32_t*>(ao + base0 + col) =
            pack_h(of[nfo][0] * inv0, of[nfo][1] * inv0);
        *reinterpret_cast<uint32_t*>(ao + base1 + col) =
            pack_h(of[nfo][2] * inv1, of[nfo][3] * inv1);
    }
}

// ---------------------------------------------------------------------------
// Host launcher
// ---------------------------------------------------------------------------
extern "C" void kernel_launch(void* const* d_in, const int* in_sizes, int n_in,
                              void* d_out, int out_size)
{
    (void)in_sizes; (void)n_in; (void)out_size;
    const float* x  = (const float*)d_in[0];
    const float* fc = (const float*)d_in[1];
    const float* wq = (const float*)d_in[2];
    const float* wk = (const float*)d_in[3];
    const float* wv = (const float*)d_in[4];
    const float* wo = (const float*)d_in[5];
    float* out = (float*)d_out;

    float* pqkv;
    __half *pxh, *pwh, *pao, *pwoh;
    __nv_bfloat16 *pqh, *pql, *pkh, *pkl, *pvth, *pvtl;
    cudaGetSymbolAddress((void**)&pqkv, g_qkv);
    cudaGetSymbolAddress((void**)&pxh,  g_xh);
    cudaGetSymbolAddress((void**)&pwh,  g_wh);
    cudaGetSymbolAddress((void**)&pao,  g_ao);
    cudaGetSymbolAddress((void**)&pwoh, g_woh);
    cudaGetSymbolAddress((void**)&pqh,  g_qh);
    cudaGetSymbolAddress((void**)&pql,  g_ql);
    cudaGetSymbolAddress((void**)&pkh,  g_kh);
    cudaGetSymbolAddress((void**)&pkl,  g_kl);
    cudaGetSymbolAddress((void**)&pvth, g_vth);
    cudaGetSymbolAddress((void**)&pvtl, g_vtl);

    cudaFuncSetAttribute(tc_gemm_f16_kernel, cudaFuncAttributeMaxDynamicSharedMemorySize,
                         GEMM_SMEM);
    cudaFuncSetAttribute(flash_tc_kernel, cudaFuncAttributeMaxDynamicSharedMemorySize, FT_SMEM);

    // fp32 -> fp16 converts
    {
        long n4 = (long)4096 * 2048 / 4;
        cvt_h_kernel<<<(unsigned)((n4 + 255) / 256), 256>>>(x, pxh, n4);
    }
    {
        long n4 = (long)2048 * 2048 / 4;
        cvt_h_kernel<<<(unsigned)((n4 + 255) / 256), 256>>>(wq, pwh, n4);
    }
    {
        long n4 = (long)512 * 2048 / 4;
        cvt_h_kernel<<<(unsigned)((n4 + 255) / 256), 256>>>(wk, pwh + (size_t)2048 * 2048, n4);
        cvt_h_kernel<<<(unsigned)((n4 + 255) / 256), 256>>>(wv, pwh + (size_t)2560 * 2048, n4);
    }

    // QKV projection (fp16 single-term): [4096,2048] x [3072,2048]^T
    tc_gemm_f16_kernel<<<dim3(3072 / GBN, 4096 / GBM), 256, GEMM_SMEM>>>(
        pxh, pwh, pqkv, 3072, 2048);

    // RoPE -> Q/K bf16 hi/lo; V transpose -> Vt bf16 hi/lo
    rope_bf16_kernel<<<20480, 256>>>(pqkv, fc, pqh, pql, pkh, pkl);
    vt_kernel<<<dim3(64, 4, 8), dim3(32, 8)>>>(pqkv, pvth, pvtl);

    // Tensor-core flash attention (split-bf16) -> attn out fp16
    flash_tc_kernel<<<dim3(32, 32), 128, FT_SMEM>>>(pqh, pql, pkh, pkl, pvth, pvtl, pao);

    // wo projection (fp16 single-term): [4096,2048] x [2048,2048]^T -> out
    {
        long n4 = (long)2048 * 2048 / 4;
        cvt_h_kernel<<<(unsigned)((n4 + 255) / 256), 256>>>(wo, pwoh, n4);
    }
    tc_gemm_f16_kernel<<<dim3(2048 / GBN, 4096 / GBM), 256, GEMM_SMEM>>>(
        pao, pwoh, out, 2048, 2048);
}